// round 7
// baseline (speedup 1.0000x reference)
#include <cuda_runtime.h>
#include <cuda_bf16.h>
#include <math.h>
#include <stdint.h>

#define NB 64
#define TT 256
#define INDIM 512
#define HH 1024
#define G3 3072
#define GRID 144
#define SPLITS 6
#define NTHREADS 256
#define STAGE_BYTES 49152
#define OFF_WH 0
#define OFF_WL 16384
#define OFF_BH 32768
#define OFF_BL 40960
#define SMEM_TOTAL (3 * STAGE_BYTES)

typedef __nv_bfloat16 bf16;

// ---------------- static device scratch ----------------
__device__ float g_gx0[(size_t)NB * TT * G3];
__device__ float g_c0[NB * HH];
__device__ float g_c1[NB * HH];
__device__ float g_part0[(size_t)SPLITS * NB * G3];
__device__ float g_part1[(size_t)SPLITS * NB * G3];
__device__ unsigned g_bar;

__device__ __align__(16) bf16 g_h0h[NB * HH];
__device__ __align__(16) bf16 g_h0l[NB * HH];
__device__ __align__(16) bf16 g_h1h[NB * HH];
__device__ __align__(16) bf16 g_h1l[NB * HH];
__device__ __align__(16) bf16 g_xh[(size_t)NB * TT * INDIM];
__device__ __align__(16) bf16 g_xl[(size_t)NB * TT * INDIM];
__device__ __align__(16) bf16 g_Wx0h[(size_t)G3 * INDIM];
__device__ __align__(16) bf16 g_Wx0l[(size_t)G3 * INDIM];
__device__ __align__(16) bf16 g_Wh0h[(size_t)G3 * HH];
__device__ __align__(16) bf16 g_Wh0l[(size_t)G3 * HH];
__device__ __align__(16) bf16 g_Wx1h[(size_t)G3 * HH];
__device__ __align__(16) bf16 g_Wx1l[(size_t)G3 * HH];
__device__ __align__(16) bf16 g_Wh1h[(size_t)G3 * HH];
__device__ __align__(16) bf16 g_Wh1l[(size_t)G3 * HH];

// ---------------- helpers ----------------
__device__ __forceinline__ float sigmoid_(float x) { return 1.0f / (1.0f + expf(-x)); }
__device__ __forceinline__ float tanh_(float x) { return 1.0f - 2.0f / (expf(2.0f * x) + 1.0f); }

__device__ __forceinline__ uint32_t smem_u32(const void* p) {
    uint32_t a;
    asm("{ .reg .u64 t; cvta.to.shared.u64 t, %1; cvt.u32.u64 %0, t; }" : "=r"(a) : "l"(p));
    return a;
}
#define SWZ(x) ((x) ^ (((x) >> 3) & 0x70))

__device__ __forceinline__ void cp16(uint32_t dst, const void* src) {
    asm volatile("cp.async.cg.shared.global [%0], [%1], 16;" :: "r"(dst), "l"(src));
}
#define CP_COMMIT() asm volatile("cp.async.commit_group;" ::: "memory")

#define LDSM4(r, addr) \
    asm volatile("ldmatrix.sync.aligned.m8n8.x4.shared.b16 {%0,%1,%2,%3}, [%4];" \
        : "=r"((r)[0]), "=r"((r)[1]), "=r"((r)[2]), "=r"((r)[3]) : "r"(addr))

#define MMA(c, a, b0, b1) \
    asm volatile("mma.sync.aligned.m16n8k16.row.col.f32.bf16.bf16.f32 " \
        "{%0,%1,%2,%3},{%4,%5,%6,%7},{%8,%9},{%0,%1,%2,%3};" \
        : "+f"((c)[0]), "+f"((c)[1]), "+f"((c)[2]), "+f"((c)[3]) \
        : "r"((a)[0]), "r"((a)[1]), "r"((a)[2]), "r"((a)[3]), "r"(b0), "r"(b1))

__device__ __forceinline__ void grid_sync(unsigned target) {
    __threadfence();
    __syncthreads();
    if (threadIdx.x == 0) {
        atomicAdd(&g_bar, 1u);
        unsigned v;
        do {
            asm volatile("ld.global.acquire.gpu.u32 %0, [%1];" : "=r"(v) : "l"(&g_bar));
        } while (v < target);
    }
    __syncthreads();
}

// ---------------- init / convert ----------------
__global__ void init_state() {
    int i = blockIdx.x * blockDim.x + threadIdx.x;
    if (i == 0) g_bar = 0u;
    if (i < NB * HH) {
        g_c0[i] = 0.f; g_c1[i] = 0.f;
        bf16 z = __float2bfloat16(0.f);
        g_h0h[i] = z; g_h0l[i] = z; g_h1h[i] = z; g_h1l[i] = z;
    }
}

#define NW0 ((size_t)G3 * INDIM)
#define NW1 ((size_t)G3 * HH)
#define NX  ((size_t)NB * TT * INDIM)

__global__ void convert_all(const float* __restrict__ x,
    const float* __restrict__ Wx0, const float* __restrict__ Wh0,
    const float* __restrict__ Wx1, const float* __restrict__ Wh1)
{
    size_t idx = (size_t)blockIdx.x * 256 + threadIdx.x;
    float v; bf16 *dh, *dl; size_t o;
    if (idx < NW0) {
        int r = (int)(idx / INDIM), k = (int)(idx % INDIM);
        int orig = r + (r >= HH ? HH : 0);     // skip f-gate rows
        v = Wx0[(size_t)orig * INDIM + k];
        dh = g_Wx0h; dl = g_Wx0l; o = idx;
    } else if (idx < NW0 + 3 * NW1) {
        size_t i2 = idx - NW0;
        int mat = (int)(i2 / NW1);
        size_t i3 = i2 % NW1;
        int r = (int)(i3 / HH), k = (int)(i3 % HH);
        int orig = r + (r >= HH ? HH : 0);
        const float* W = mat == 0 ? Wh0 : (mat == 1 ? Wx1 : Wh1);
        v = W[(size_t)orig * HH + k];
        dh = mat == 0 ? g_Wh0h : (mat == 1 ? g_Wx1h : g_Wh1h);
        dl = mat == 0 ? g_Wh0l : (mat == 1 ? g_Wx1l : g_Wh1l);
        o = i3;
    } else {
        size_t i2 = idx - NW0 - 3 * NW1;
        if (i2 >= NX) return;
        v = x[i2]; dh = g_xh; dl = g_xl; o = i2;
    }
    bf16 h = __float2bfloat16(v);
    dh[o] = h;
    dl[o] = __float2bfloat16(v - __bfloat162float(h));
}

// ---------------- tile loads (256 threads) ----------------
__device__ __forceinline__ void load_W(uint32_t sbase,
    const bf16* __restrict__ Wh, const bf16* __restrict__ Wl, int k0, int ws, int tid)
{
#pragma unroll
    for (int i = 0; i < 4; i++) {
        int seg = tid + i * NTHREADS;          // 0..1023: 128 rows x 8 segs
        int row = seg >> 3, sc = seg & 7;
        uint32_t so = SWZ((uint32_t)(row * 128 + sc * 16));
        size_t off = (size_t)row * ws + k0 + sc * 8;
        cp16(sbase + OFF_WH + so, Wh + off);
        cp16(sbase + OFF_WL + so, Wl + off);
    }
}
__device__ __forceinline__ void load_B(uint32_t sbase,
    const bf16* __restrict__ Bh, const bf16* __restrict__ Bl, int k0, int bs, int tid)
{
#pragma unroll
    for (int i = 0; i < 2; i++) {
        int seg = tid + i * NTHREADS;          // 0..511: 64 rows x 8 segs
        int row = seg >> 3, sc = seg & 7;
        uint32_t so = SWZ((uint32_t)(row * 128 + sc * 16));
        size_t off = (size_t)row * bs + k0 + sc * 8;
        cp16(sbase + OFF_BH + so, Bh + off);
        cp16(sbase + OFF_BL + so, Bl + off);
    }
}

// ---------------- warp MMA ----------------
// 8 warps: kh = wid&1 (K half), warpM = (wid>>1)&1 (64 gate rows), warpN = wid>>2 (32 batch).
// Warp tile 64(M) x 32(N) over 32 of the 64 K elements.
__device__ __forceinline__ void compute_chunk(uint32_t stage, float acc[4][4][4],
                                              int lane, int kh, int warpM, int warpN)
{
#pragma unroll
    for (int q = 0; q < 2; q++) {
        const int kByte = (kh * 2 + q) * 32;
        uint32_t ah[4][4], al[4][4];
#pragma unroll
        for (int mt = 0; mt < 4; mt++) {
            int row = warpM * 64 + mt * 16 + (lane & 7) + ((lane >> 3) & 1) * 8;
            int col = kByte + ((lane >> 4) << 4);
            uint32_t a = SWZ((uint32_t)(row * 128 + col));
            LDSM4(ah[mt], stage + OFF_WH + a);
            LDSM4(al[mt], stage + OFF_WL + a);
        }
        uint32_t bh[2][4], bl[2][4];
#pragma unroll
        for (int p = 0; p < 2; p++) {
            int row = warpN * 32 + p * 16 + (lane & 7) + ((lane >> 4) & 1) * 8;
            int col = kByte + (((lane >> 3) & 1) << 4);
            uint32_t a = SWZ((uint32_t)(row * 128 + col));
            LDSM4(bh[p], stage + OFF_BH + a);
            LDSM4(bl[p], stage + OFF_BL + a);
        }
#pragma unroll
        for (int mt = 0; mt < 4; mt++)
#pragma unroll
            for (int nt = 0; nt < 4; nt++) {
                int p = nt >> 1, hf = nt & 1;
                MMA(acc[mt][nt], ah[mt], bh[p][hf * 2], bh[p][hf * 2 + 1]);
                MMA(acc[mt][nt], ah[mt], bl[p][hf * 2], bl[p][hf * 2 + 1]);
                MMA(acc[mt][nt], al[mt], bh[p][hf * 2], bh[p][hf * 2 + 1]);
            }
    }
}

// pf: 0 = load all of chunk lo, 1 = W prefetched, 2 = W+B prefetched
template <typename F>
__device__ __forceinline__ void gemm_tile(uint32_t tiles, int lo, int NC, int pf,
                                          F&& get, float acc[4][4][4])
{
    const int tid = threadIdx.x;
    const int lane = tid & 31, wid = tid >> 5;
    const int kh = wid & 1, warpM = (wid >> 1) & 1, warpN = wid >> 2;

    auto ld_full = [&](int c) {   // c local
        const bf16 *Wh, *Wl, *Bh, *Bl; int k0, ws, bs;
        get(lo + c, Wh, Wl, Bh, Bl, k0, ws, bs);
        uint32_t sb = tiles + (c % 3) * STAGE_BYTES;
        load_W(sb, Wh, Wl, k0, ws, tid);
        load_B(sb, Bh, Bl, k0, bs, tid);
        CP_COMMIT();
    };
    {   // chunk 0: respect prefetch flag; commit collects prefetched cp.asyncs
        const bf16 *Wh, *Wl, *Bh, *Bl; int k0, ws, bs;
        get(lo, Wh, Wl, Bh, Bl, k0, ws, bs);
        if (pf < 1) load_W(tiles, Wh, Wl, k0, ws, tid);
        if (pf < 2) load_B(tiles, Bh, Bl, k0, bs, tid);
        CP_COMMIT();
    }
    if (NC > 1) ld_full(1);
    for (int c = 0; c < NC; c++) {
        if (c + 1 < NC) { asm volatile("cp.async.wait_group 1;" ::: "memory"); }
        else            { asm volatile("cp.async.wait_group 0;" ::: "memory"); }
        __syncthreads();                     // stage c visible; stage c-1 free
        if (c + 2 < NC) ld_full(c + 2);
        compute_chunk(tiles + (c % 3) * STAGE_BYTES, acc, lane, kh, warpM, warpN);
    }
    __syncthreads();                         // all stages idle now
}

// Reduce kh pairs via stage2 scratch. After this, kh==0 warps hold the full sum.
__device__ __forceinline__ void reduce_kh(uint32_t tiles, float acc[4][4][4],
                                          int lane, int kh, int warpM, int warpN)
{
    uint32_t red = tiles + 2 * STAGE_BYTES + (uint32_t)(warpM * 2 + warpN) * 8192;
    if (kh == 1) {
#pragma unroll
        for (int mt = 0; mt < 4; mt++)
#pragma unroll
            for (int nt = 0; nt < 4; nt++) {
                uint32_t a = red + (uint32_t)(mt * 4 + nt) * 512 + lane * 16;
                asm volatile("st.shared.v4.f32 [%0], {%1,%2,%3,%4};" :: "r"(a),
                    "f"(acc[mt][nt][0]), "f"(acc[mt][nt][1]),
                    "f"(acc[mt][nt][2]), "f"(acc[mt][nt][3]));
            }
    }
    __syncthreads();
    if (kh == 0) {
#pragma unroll
        for (int mt = 0; mt < 4; mt++)
#pragma unroll
            for (int nt = 0; nt < 4; nt++) {
                uint32_t a = red + (uint32_t)(mt * 4 + nt) * 512 + lane * 16;
                float v0, v1, v2, v3;
                asm volatile("ld.shared.v4.f32 {%0,%1,%2,%3}, [%4];"
                    : "=f"(v0), "=f"(v1), "=f"(v2), "=f"(v3) : "r"(a));
                acc[mt][nt][0] += v0; acc[mt][nt][1] += v1;
                acc[mt][nt][2] += v2; acc[mt][nt][3] += v3;
            }
    }
}

#define ZERO_ACC(acc) do { \
_Pragma("unroll") for (int i = 0; i < 4; i++) \
_Pragma("unroll") for (int j = 0; j < 4; j++) \
_Pragma("unroll") for (int k = 0; k < 4; k++) (acc)[i][j][k] = 0.f; } while (0)

// ---------------- chunk pointer logic (recurrent) ----------------
template <int LAYER>
__device__ __forceinline__ void get_rec(int col0, int c,
    const bf16*& Wh, const bf16*& Wl, const bf16*& Bh, const bf16*& Bl, int& k0)
{
    if (LAYER == 0) {
        k0 = c * 64;
        Wh = g_Wh0h + (size_t)col0 * HH; Wl = g_Wh0l + (size_t)col0 * HH;
        Bh = g_h0h; Bl = g_h0l;
    } else if (c < 16) {
        k0 = c * 64;
        Wh = g_Wx1h + (size_t)col0 * HH; Wl = g_Wx1l + (size_t)col0 * HH;
        Bh = g_h0h; Bl = g_h0l;
    } else {
        k0 = (c - 16) * 64;
        Wh = g_Wh1h + (size_t)col0 * HH; Wl = g_Wh1l + (size_t)col0 * HH;
        Bh = g_h1h; Bl = g_h1l;
    }
}

template <int LAYER>
__device__ __forceinline__ void prefetch0(uint32_t tiles, bool doB) {
    const int ct = blockIdx.x / SPLITS;
    const int sp = blockIdx.x % SPLITS;
    const int col0 = ct * 128;
    const int CH = (LAYER == 0) ? 16 : 32;
    const int lo = (sp * CH) / SPLITS;
    const bf16 *Wh, *Wl, *Bh, *Bl; int k0;
    get_rec<LAYER>(col0, lo, Wh, Wl, Bh, Bl, k0);
    load_W(tiles, Wh, Wl, k0, HH, threadIdx.x);
    if (doB) load_B(tiles, Bh, Bl, k0, HH, threadIdx.x);
}

// ---------------- precompute gx0 ----------------
__global__ __launch_bounds__(NTHREADS, 1) void precompute_tc(const float* __restrict__ b0) {
    extern __shared__ char smem[];
    uint32_t tiles = smem_u32(smem);
    const int ct = blockIdx.x % 24;
    const int nt0 = (blockIdx.x / 24) * 64;
    const int col0 = ct * 128;
    const int lane = threadIdx.x & 31, wid = threadIdx.x >> 5;
    const int kh = wid & 1, warpM = (wid >> 1) & 1, warpN = wid >> 2;

    float acc[4][4][4];
    ZERO_ACC(acc);

    auto get = [&](int c, const bf16*& Wh, const bf16*& Wl,
                   const bf16*& Bh, const bf16*& Bl, int& k0, int& ws, int& bs) {
        ws = INDIM; bs = INDIM; k0 = c * 64;
        Wh = g_Wx0h + (size_t)col0 * INDIM; Wl = g_Wx0l + (size_t)col0 * INDIM;
        Bh = g_xh + (size_t)nt0 * INDIM;    Bl = g_xl + (size_t)nt0 * INDIM;
    };
    gemm_tile(tiles, 0, INDIM / 64, 0, get, acc);
    reduce_kh(tiles, acc, lane, kh, warpM, warpN);

    if (kh == 0) {
        const int g = lane >> 2, tig = lane & 3;
#pragma unroll
        for (int mt = 0; mt < 4; mt++) {
            int colA = col0 + warpM * 64 + mt * 16 + g;
            float bias0 = b0[colA + (colA >= HH ? HH : 0)];
            float bias8 = b0[colA + 8 + (colA + 8 >= HH ? HH : 0)];
#pragma unroll
            for (int nt = 0; nt < 4; nt++) {
                int r = nt0 + warpN * 32 + nt * 8 + tig * 2;
                g_gx0[(size_t)r * G3 + colA] = acc[mt][nt][0] + bias0;
                g_gx0[(size_t)(r + 1) * G3 + colA] = acc[mt][nt][1] + bias0;
                g_gx0[(size_t)r * G3 + colA + 8] = acc[mt][nt][2] + bias8;
                g_gx0[(size_t)(r + 1) * G3 + colA + 8] = acc[mt][nt][3] + bias8;
            }
        }
    }
}

// ---------------- recurrent phases ----------------
template <int LAYER>
__device__ __forceinline__ void gemm_phase(uint32_t tiles, float* __restrict__ part, int pf) {
    const int ct = blockIdx.x / SPLITS;
    const int sp = blockIdx.x % SPLITS;
    const int col0 = ct * 128;
    const int CH = (LAYER == 0) ? 16 : 32;
    const int lo = (sp * CH) / SPLITS;
    const int hi = ((sp + 1) * CH) / SPLITS;
    const int lane = threadIdx.x & 31, wid = threadIdx.x >> 5;
    const int kh = wid & 1, warpM = (wid >> 1) & 1, warpN = wid >> 2;

    float acc[4][4][4];
    ZERO_ACC(acc);

    auto get = [&](int c, const bf16*& Wh, const bf16*& Wl,
                   const bf16*& Bh, const bf16*& Bl, int& k0, int& ws, int& bs) {
        ws = HH; bs = HH;
        get_rec<LAYER>(col0, c, Wh, Wl, Bh, Bl, k0);
    };
    gemm_tile(tiles, lo, hi - lo, pf, get, acc);
    reduce_kh(tiles, acc, lane, kh, warpM, warpN);

    if (kh == 0) {
        const int g = lane >> 2, tig = lane & 3;
#pragma unroll
        for (int mt = 0; mt < 4; mt++) {
            int colA = col0 + warpM * 64 + mt * 16 + g;
#pragma unroll
            for (int nt = 0; nt < 4; nt++) {
                int b = warpN * 32 + nt * 8 + tig * 2;
                float* p0 = part + ((size_t)sp * NB + b) * G3;
                p0[colA] = acc[mt][nt][0];
                p0[G3 + colA] = acc[mt][nt][1];
                p0[colA + 8] = acc[mt][nt][2];
                p0[G3 + colA + 8] = acc[mt][nt][3];
            }
        }
    }
}

template <int LAYER>
__device__ __forceinline__ void pointwise(const float* __restrict__ part,
    const float* __restrict__ bias, const float* __restrict__ Wc,
    float* __restrict__ out, int t)
{
    for (int cell = blockIdx.x * NTHREADS + threadIdx.x; cell < NB * HH;
         cell += GRID * NTHREADS) {
        int b = cell >> 10, j = cell & (HH - 1);
        float si = 0.f, sg = 0.f, so = 0.f;
#pragma unroll
        for (int sp = 0; sp < SPLITS; sp++) {
            const float* p = part + ((size_t)sp * NB + b) * G3 + j;
            si += p[0]; sg += p[HH]; so += p[2 * HH];
        }
        float pi, pg, po;
        if (LAYER == 0) {
            const float* gx = &g_gx0[((size_t)b * TT + t) * G3 + j];
            pi = si + gx[0]; pg = sg + gx[HH]; po = so + gx[2 * HH];
        } else {
            pi = si + bias[j]; pg = sg + bias[2 * HH + j]; po = so + bias[3 * HH + j];
        }
        float* cb = (LAYER == 0) ? g_c0 : g_c1;
        float c = cb[cell];
        float ig = sigmoid_(pi + Wc[j] * c);
        float gg = tanh_(pg);
        float og = sigmoid_(po + Wc[2 * HH + j] * c);
        float cn = gg * (c + ig);      // faithful: forget gate unused
        float hn = og * tanh_(c);      // faithful: uses OLD cell state
        cb[cell] = cn;
        bf16 hh = __float2bfloat16(hn);
        bf16 hl = __float2bfloat16(hn - __bfloat162float(hh));
        if (LAYER == 0) {
            g_h0h[cell] = hh; g_h0l[cell] = hl;
        } else {
            g_h1h[cell] = hh; g_h1l[cell] = hl;
            out[((size_t)b * TT + t) * HH + j] = hn;
            if (t == TT - 1) {
                out[(size_t)NB * TT * HH + cell] = hn;
                out[(size_t)NB * TT * HH + NB * HH + cell] = cn;
            }
        }
    }
}

__global__ __launch_bounds__(NTHREADS, 1) void lstm_persistent(
    const float* __restrict__ b1, const float* __restrict__ Wc0,
    const float* __restrict__ Wc1, float* __restrict__ out)
{
    extern __shared__ char smem[];
    uint32_t tiles = smem_u32(smem);
    unsigned gen = 0;
    int pf0 = 0;
    for (int t = 0; t < TT; t++) {
        gemm_phase<0>(tiles, g_part0, pf0);
        prefetch0<1>(tiles, false);            // W of gemm1 chunk0 (static) -> stage0
        grid_sync(++gen * GRID);
        pointwise<0>(g_part0, nullptr, Wc0, out, t);
        grid_sync(++gen * GRID);
        gemm_phase<1>(tiles, g_part1, 1);      // W prefetched; B loaded now
        if (t + 1 < TT) {
            prefetch0<0>(tiles, true);         // W=Wh0, B=h0(t) final since sync#2
            pf0 = 2;
        }
        grid_sync(++gen * GRID);
        pointwise<1>(g_part1, b1, Wc1, out, t);
        // pw<1>(t) vs gemm<0>(t+1): disjoint buffers; syncs #1/#2 of step t+1
        // order pw<1>(t) before gemm<1>(t+1)'s h1 reads.
    }
}

// ---------------- host launch ----------------
extern "C" void kernel_launch(void* const* d_in, const int* in_sizes, int n_in,
                              void* d_out, int out_size) {
    const float* x   = (const float*)d_in[0];
    const float* Wx0 = (const float*)d_in[1];
    const float* Wh0 = (const float*)d_in[2];
    const float* b0  = (const float*)d_in[3];
    const float* Wc0 = (const float*)d_in[4];
    const float* Wx1 = (const float*)d_in[5];
    const float* Wh1 = (const float*)d_in[6];
    const float* b1  = (const float*)d_in[7];
    const float* Wc1 = (const float*)d_in[8];
    float* out = (float*)d_out;

    cudaFuncSetAttribute(precompute_tc,
                         cudaFuncAttributeMaxDynamicSharedMemorySize, SMEM_TOTAL);
    cudaFuncSetAttribute(lstm_persistent,
                         cudaFuncAttributeMaxDynamicSharedMemorySize, SMEM_TOTAL);

    size_t total_conv = NW0 + 3 * NW1 + NX;
    int conv_blocks = (int)((total_conv + 255) / 256);

    init_state<<<256, 256>>>();
    convert_all<<<conv_blocks, 256>>>(x, Wx0, Wh0, Wx1, Wh1);
    precompute_tc<<<24 * (NB * TT / 64), NTHREADS, SMEM_TOTAL>>>(b0);
    lstm_persistent<<<GRID, NTHREADS, SMEM_TOTAL>>>(b1, Wc0, Wc1, out);
}

// round 8
// speedup vs baseline: 1.0262x; 1.0262x over previous
#include <cuda_runtime.h>
#include <cuda_bf16.h>
#include <math.h>
#include <stdint.h>

#define NB 64
#define TT 256
#define HH 1024
#define G3 3072
#define GRID 144
#define SPLITS 6
#define NTHREADS 512
#define STAGE_BYTES 49152
#define OFF_WH 0
#define OFF_WL 16384
#define OFF_BH 32768
#define OFF_BL 40960
#define SMEM_TOTAL (3 * STAGE_BYTES)

typedef __nv_bfloat16 bf16;

// ---------------- static device scratch ----------------
__device__ float g_c0[NB * HH];
__device__ float g_c1[NB * HH];
__device__ float g_part0[(size_t)SPLITS * NB * G3];
__device__ float g_part1[(size_t)SPLITS * NB * G3];
__device__ unsigned g_count, g_sense;

__device__ __align__(16) bf16 g_h0h[NB * HH];
__device__ __align__(16) bf16 g_h0l[NB * HH];
__device__ __align__(16) bf16 g_h1h[NB * HH];
__device__ __align__(16) bf16 g_h1l[NB * HH];
__device__ __align__(16) bf16 g_xh[(size_t)NB * TT * 512];
__device__ __align__(16) bf16 g_xl[(size_t)NB * TT * 512];
// W0 = [Wx0 | Wh0] packed gate-rows [i|g|o], [3072][1536]
__device__ __align__(16) bf16 g_W0h[(size_t)G3 * 1536];
__device__ __align__(16) bf16 g_W0l[(size_t)G3 * 1536];
// W1 = [Wx1 | Wh1], [3072][2048]
__device__ __align__(16) bf16 g_W1h[(size_t)G3 * 2048];
__device__ __align__(16) bf16 g_W1l[(size_t)G3 * 2048];

// ---------------- helpers ----------------
__device__ __forceinline__ float sigmoid_(float x) { return 1.0f / (1.0f + expf(-x)); }
__device__ __forceinline__ float tanh_(float x) { return 1.0f - 2.0f / (expf(2.0f * x) + 1.0f); }

__device__ __forceinline__ uint32_t smem_u32(const void* p) {
    uint32_t a;
    asm("{ .reg .u64 t; cvta.to.shared.u64 t, %1; cvt.u32.u64 %0, t; }" : "=r"(a) : "l"(p));
    return a;
}
#define SWZ(x) ((x) ^ (((x) >> 3) & 0x70))

__device__ __forceinline__ void cp16(uint32_t dst, const void* src) {
    asm volatile("cp.async.cg.shared.global [%0], [%1], 16;" :: "r"(dst), "l"(src));
}
#define CP_COMMIT() asm volatile("cp.async.commit_group;" ::: "memory")

#define LDSM4(r, addr) \
    asm volatile("ldmatrix.sync.aligned.m8n8.x4.shared.b16 {%0,%1,%2,%3}, [%4];" \
        : "=r"((r)[0]), "=r"((r)[1]), "=r"((r)[2]), "=r"((r)[3]) : "r"(addr))

#define MMA(c, a, b0, b1) \
    asm volatile("mma.sync.aligned.m16n8k16.row.col.f32.bf16.bf16.f32 " \
        "{%0,%1,%2,%3},{%4,%5,%6,%7},{%8,%9},{%0,%1,%2,%3};" \
        : "+f"((c)[0]), "+f"((c)[1]), "+f"((c)[2]), "+f"((c)[3]) \
        : "r"((a)[0]), "r"((a)[1]), "r"((a)[2]), "r"((a)[3]), "r"(b0), "r"(b1))

// sense-reversing grid barrier: bounded state, replay/launch consistent
__device__ __forceinline__ void grid_sync(int& sense) {
    sense ^= 1;
    __syncthreads();
    if (threadIdx.x == 0) {
        __threadfence();
        unsigned old = atomicAdd(&g_count, 1u);
        if (old == GRID - 1) {
            g_count = 0;
            asm volatile("st.global.release.gpu.u32 [%0], %1;"
                         :: "l"(&g_sense), "r"((unsigned)sense));
        } else {
            unsigned v;
            do {
                asm volatile("ld.global.acquire.gpu.u32 %0, [%1];"
                             : "=r"(v) : "l"(&g_sense));
            } while (v != (unsigned)sense);
        }
    }
    __syncthreads();
}

// ---------------- init / convert ----------------
__global__ void init_state() {
    int i = blockIdx.x * blockDim.x + threadIdx.x;
    if (i == 0) { g_count = 0u; g_sense = 0u; }
    if (i < NB * HH) {
        g_c0[i] = 0.f; g_c1[i] = 0.f;
        bf16 z = __float2bfloat16(0.f);
        g_h0h[i] = z; g_h0l[i] = z; g_h1h[i] = z; g_h1l[i] = z;
    }
}

#define NW0E ((size_t)G3 * 1536)
#define NW1E ((size_t)G3 * 2048)
#define NXE  ((size_t)NB * TT * 512)

__global__ void convert_all(const float* __restrict__ x,
    const float* __restrict__ Wx0, const float* __restrict__ Wh0,
    const float* __restrict__ Wx1, const float* __restrict__ Wh1)
{
    size_t idx = (size_t)blockIdx.x * 256 + threadIdx.x;
    float v; bf16 *dh, *dl; size_t o;
    if (idx < NW0E) {
        int r = (int)(idx / 1536), k = (int)(idx % 1536);
        int R = r + (r >= HH ? HH : 0);        // packed [i|g|o] -> orig [i,f,g,o]
        v = (k < 512) ? Wx0[(size_t)R * 512 + k] : Wh0[(size_t)R * HH + (k - 512)];
        dh = g_W0h; dl = g_W0l; o = idx;
    } else if (idx < NW0E + NW1E) {
        size_t i2 = idx - NW0E;
        int r = (int)(i2 / 2048), k = (int)(i2 % 2048);
        int R = r + (r >= HH ? HH : 0);
        v = (k < HH) ? Wx1[(size_t)R * HH + k] : Wh1[(size_t)R * HH + (k - HH)];
        dh = g_W1h; dl = g_W1l; o = i2;
    } else {
        size_t i2 = idx - NW0E - NW1E;
        if (i2 >= NXE) return;
        v = x[i2]; dh = g_xh; dl = g_xl; o = i2;
    }
    bf16 h = __float2bfloat16(v);
    dh[o] = h;
    dl[o] = __float2bfloat16(v - __bfloat162float(h));
}

// ---------------- tile loads (512 threads) ----------------
__device__ __forceinline__ void load_W(uint32_t sbase,
    const bf16* __restrict__ Wh, const bf16* __restrict__ Wl, int k0, int ws, int tid)
{
#pragma unroll
    for (int i = 0; i < 2; i++) {
        int seg = tid + i * NTHREADS;          // 0..1023: 128 rows x 8 segs
        int row = seg >> 3, sc = seg & 7;
        uint32_t so = SWZ((uint32_t)(row * 128 + sc * 16));
        size_t off = (size_t)row * ws + k0 + sc * 8;
        cp16(sbase + OFF_WH + so, Wh + off);
        cp16(sbase + OFF_WL + so, Wl + off);
    }
}
__device__ __forceinline__ void load_B(uint32_t sbase,
    const bf16* __restrict__ Bh, const bf16* __restrict__ Bl, int k0, int bs, int tid)
{
    int row = tid >> 3, sc = tid & 7;          // 64 rows x 8 segs = 512
    uint32_t so = SWZ((uint32_t)(row * 128 + sc * 16));
    size_t off = (size_t)row * bs + k0 + sc * 8;
    cp16(sbase + OFF_BH + so, Bh + off);
    cp16(sbase + OFF_BL + so, Bl + off);
}

// ---------------- chunk pointer logic ----------------
// LAYER 0: K = 1536 = [x_t (512) | h0 (1024)], chunks 0..23
// LAYER 1: K = 2048 = [h0 | h1], chunks 0..31
template <int LAYER>
__device__ __forceinline__ void get_rec(int col0, int c, int t,
    const bf16*& Wh, const bf16*& Wl, int& wk0, int& ws,
    const bf16*& Bh, const bf16*& Bl, int& bk0, int& bs)
{
    if (LAYER == 0) {
        ws = 1536; wk0 = c * 64;
        Wh = g_W0h + (size_t)col0 * 1536; Wl = g_W0l + (size_t)col0 * 1536;
        if (c < 8) { Bh = g_xh + (size_t)t * 512; Bl = g_xl + (size_t)t * 512;
                     bs = TT * 512; bk0 = c * 64; }
        else       { Bh = g_h0h; Bl = g_h0l; bs = HH; bk0 = (c - 8) * 64; }
    } else {
        ws = 2048; wk0 = c * 64;
        Wh = g_W1h + (size_t)col0 * 2048; Wl = g_W1l + (size_t)col0 * 2048;
        if (c < 16) { Bh = g_h0h; Bl = g_h0l; bs = HH; bk0 = c * 64; }
        else        { Bh = g_h1h; Bl = g_h1l; bs = HH; bk0 = (c - 16) * 64; }
    }
}

// ---------------- warp MMA (16 warps: 4M x 4N) ----------------
__device__ __forceinline__ void compute_chunk(uint32_t stage, float acc[2][2][4],
                                              int lane, int warpM, int warpN)
{
#pragma unroll
    for (int kk = 0; kk < 4; kk++) {
        const int kByte = kk * 32;
        uint32_t ah[2][4], al[2][4];
#pragma unroll
        for (int mt = 0; mt < 2; mt++) {
            int row = warpM * 32 + mt * 16 + (lane & 7) + ((lane >> 3) & 1) * 8;
            int col = kByte + ((lane >> 4) << 4);
            uint32_t a = SWZ((uint32_t)(row * 128 + col));
            LDSM4(ah[mt], stage + OFF_WH + a);
            LDSM4(al[mt], stage + OFF_WL + a);
        }
        uint32_t bh[4], bl[4];
        {
            int row = warpN * 16 + (lane & 7) + ((lane >> 4) & 1) * 8;
            int col = kByte + (((lane >> 3) & 1) << 4);
            uint32_t a = SWZ((uint32_t)(row * 128 + col));
            LDSM4(bh, stage + OFF_BH + a);
            LDSM4(bl, stage + OFF_BL + a);
        }
#pragma unroll
        for (int mt = 0; mt < 2; mt++)
#pragma unroll
            for (int nt = 0; nt < 2; nt++) {
                MMA(acc[mt][nt], ah[mt], bh[nt * 2], bh[nt * 2 + 1]);
                MMA(acc[mt][nt], ah[mt], bl[nt * 2], bl[nt * 2 + 1]);
                MMA(acc[mt][nt], al[mt], bh[nt * 2], bh[nt * 2 + 1]);
            }
    }
}

// pf: 0 = load all of chunk lo, 1 = W prefetched, 2 = W+B prefetched
template <int LAYER>
__device__ __forceinline__ void gemm_phase(uint32_t tiles, float* __restrict__ part,
                                           int pf, int t)
{
    const int ct = blockIdx.x / SPLITS;
    const int sp = blockIdx.x % SPLITS;
    const int col0 = ct * 128;
    const int CH = (LAYER == 0) ? 24 : 32;
    const int lo = (sp * CH) / SPLITS;
    const int hi = ((sp + 1) * CH) / SPLITS;
    const int NC = hi - lo;
    const int tid = threadIdx.x;
    const int lane = tid & 31, wid = tid >> 5;
    const int warpM = wid & 3, warpN = wid >> 2;

    float acc[2][2][4];
#pragma unroll
    for (int i = 0; i < 2; i++)
#pragma unroll
        for (int j = 0; j < 2; j++)
#pragma unroll
            for (int k = 0; k < 4; k++) acc[i][j][k] = 0.f;

    auto ld_full = [&](int cl) {
        const bf16 *Wh, *Wl, *Bh, *Bl; int wk0, ws, bk0, bs;
        get_rec<LAYER>(col0, lo + cl, t, Wh, Wl, wk0, ws, Bh, Bl, bk0, bs);
        uint32_t sb = tiles + (cl % 3) * STAGE_BYTES;
        load_W(sb, Wh, Wl, wk0, ws, tid);
        load_B(sb, Bh, Bl, bk0, bs, tid);
        CP_COMMIT();
    };
    {
        const bf16 *Wh, *Wl, *Bh, *Bl; int wk0, ws, bk0, bs;
        get_rec<LAYER>(col0, lo, t, Wh, Wl, wk0, ws, Bh, Bl, bk0, bs);
        if (pf < 1) load_W(tiles, Wh, Wl, wk0, ws, tid);
        if (pf < 2) load_B(tiles, Bh, Bl, bk0, bs, tid);
        CP_COMMIT();
    }
    if (NC > 1) ld_full(1);
    for (int c = 0; c < NC; c++) {
        if (c + 1 < NC) { asm volatile("cp.async.wait_group 1;" ::: "memory"); }
        else            { asm volatile("cp.async.wait_group 0;" ::: "memory"); }
        __syncthreads();
        if (c + 2 < NC) ld_full(c + 2);
        compute_chunk(tiles + (c % 3) * STAGE_BYTES, acc, lane, warpM, warpN);
    }
    __syncthreads();   // stages idle; safe for cross-phase prefetch into stage0

    const int g = lane >> 2, tig = lane & 3;
#pragma unroll
    for (int mt = 0; mt < 2; mt++) {
        int colA = col0 + warpM * 32 + mt * 16 + g;
#pragma unroll
        for (int nt = 0; nt < 2; nt++) {
            int b = warpN * 16 + nt * 8 + tig * 2;
            float* p0 = part + ((size_t)sp * NB + b) * G3;
            p0[colA] = acc[mt][nt][0];
            p0[G3 + colA] = acc[mt][nt][1];
            p0[colA + 8] = acc[mt][nt][2];
            p0[G3 + colA + 8] = acc[mt][nt][3];
        }
    }
}

// prefetch W (and optionally B) of first chunk of phase LAYER into stage 0 (no commit)
template <int LAYER>
__device__ __forceinline__ void prefetch0(uint32_t tiles, bool doB, int t) {
    const int sp = blockIdx.x % SPLITS;
    const int col0 = (blockIdx.x / SPLITS) * 128;
    const int CH = (LAYER == 0) ? 24 : 32;
    const int lo = (sp * CH) / SPLITS;
    const bf16 *Wh, *Wl, *Bh, *Bl; int wk0, ws, bk0, bs;
    get_rec<LAYER>(col0, lo, t, Wh, Wl, wk0, ws, Bh, Bl, bk0, bs);
    load_W(tiles, Wh, Wl, wk0, ws, threadIdx.x);
    if (doB) load_B(tiles, Bh, Bl, bk0, bs, threadIdx.x);
}

// ---------------- pointwise ----------------
template <int LAYER>
__device__ __forceinline__ void pointwise(const float* __restrict__ part,
    const float* __restrict__ bias, const float* __restrict__ Wc,
    float* __restrict__ out, int t)
{
    int cell = blockIdx.x * NTHREADS + threadIdx.x;
    if (cell >= NB * HH) return;
    int b = cell >> 10, j = cell & (HH - 1);
    float si = 0.f, sg = 0.f, so = 0.f;
#pragma unroll
    for (int sp = 0; sp < SPLITS; sp++) {
        const float* p = part + ((size_t)sp * NB + b) * G3 + j;
        si += p[0]; sg += p[HH]; so += p[2 * HH];
    }
    // bias: orig concat [i,f,g,o]; i: j, g: 2H+j, o: 3H+j
    float pi = si + bias[j];
    float pg = sg + bias[2 * HH + j];
    float po = so + bias[3 * HH + j];
    float* cb = (LAYER == 0) ? g_c0 : g_c1;
    float c = cb[cell];
    float ig = sigmoid_(pi + Wc[j] * c);
    float gg = tanh_(pg);
    float og = sigmoid_(po + Wc[2 * HH + j] * c);
    float cn = gg * (c + ig);      // faithful: forget gate unused
    float hn = og * tanh_(c);      // faithful: uses OLD cell state
    cb[cell] = cn;
    bf16 hh = __float2bfloat16(hn);
    bf16 hl = __float2bfloat16(hn - __bfloat162float(hh));
    if (LAYER == 0) {
        g_h0h[cell] = hh; g_h0l[cell] = hl;
    } else {
        g_h1h[cell] = hh; g_h1l[cell] = hl;
        out[((size_t)b * TT + t) * HH + j] = hn;
        if (t == TT - 1) {
            out[(size_t)NB * TT * HH + cell] = hn;
            out[(size_t)NB * TT * HH + NB * HH + cell] = cn;
        }
    }
}

__global__ __launch_bounds__(NTHREADS, 1) void lstm_persistent(
    const float* __restrict__ b0, const float* __restrict__ b1,
    const float* __restrict__ Wc0, const float* __restrict__ Wc1,
    float* __restrict__ out)
{
    extern __shared__ char smem[];
    uint32_t tiles = smem_u32(smem);
    int sense = 0;
    int pf0 = 0;
    for (int t = 0; t < TT; t++) {
        gemm_phase<0>(tiles, g_part0, pf0, t);   // gates0 = [x_t|h0(t-1)] . W0^T
        prefetch0<1>(tiles, false, t);           // W of gemm1 chunk0 (static)
        grid_sync(sense);
        pointwise<0>(g_part0, b0, Wc0, out, t);  // writes h0(t)
        grid_sync(sense);
        gemm_phase<1>(tiles, g_part1, 1, t);     // gates1 = [h0(t)|h1(t-1)] . W1^T
        if (t + 1 < TT) {
            prefetch0<0>(tiles, true, t + 1);    // W0 + B (x(t+1) or h0(t), both final)
            pf0 = 2;
        }
        grid_sync(sense);
        pointwise<1>(g_part1, b1, Wc1, out, t);  // writes h1(t), out
        // pw<1>(t) ordered before gemm<1>(t+1)'s h1/part1 reads by syncs of step t+1
    }
}

// ---------------- host launch ----------------
extern "C" void kernel_launch(void* const* d_in, const int* in_sizes, int n_in,
                              void* d_out, int out_size) {
    const float* x   = (const float*)d_in[0];
    const float* Wx0 = (const float*)d_in[1];
    const float* Wh0 = (const float*)d_in[2];
    const float* b0  = (const float*)d_in[3];
    const float* Wc0 = (const float*)d_in[4];
    const float* Wx1 = (const float*)d_in[5];
    const float* Wh1 = (const float*)d_in[6];
    const float* b1  = (const float*)d_in[7];
    const float* Wc1 = (const float*)d_in[8];
    float* out = (float*)d_out;

    cudaFuncSetAttribute(lstm_persistent,
                         cudaFuncAttributeMaxDynamicSharedMemorySize, SMEM_TOTAL);

    size_t total_conv = NW0E + NW1E + NXE;
    int conv_blocks = (int)((total_conv + 255) / 256);

    init_state<<<256, 256>>>();
    convert_all<<<conv_blocks, 256>>>(x, Wx0, Wh0, Wx1, Wh1);
    lstm_persistent<<<GRID, NTHREADS, SMEM_TOTAL>>>(b0, b1, Wc0, Wc1, out);
}

// round 9
// speedup vs baseline: 1.2631x; 1.2309x over previous
#include <cuda_runtime.h>
#include <cuda_fp16.h>
#include <math.h>
#include <stdint.h>

#define NB 64
#define TT 256
#define HH 1024
#define G3 3072
#define GRID 144
#define SPLITS 6
#define NTHREADS 512
#define K0 1536
#define K1 2048
#define CH0 24
#define CH1 32
#define W0_OFF 0
#define W1_OFF 65536
#define B_OFF 163840
#define B_STAGE 16384
#define SMEM_TOTAL 212992

typedef __half h16;

// ---------------- static device scratch ----------------
__device__ float g_c0[NB * HH];
__device__ float g_c1[NB * HH];
__device__ float g_part0[(size_t)SPLITS * NB * G3];
__device__ float g_part1[(size_t)SPLITS * NB * G3];
__device__ unsigned g_count, g_sense;

__device__ __align__(16) h16 g_h0h[NB * HH];
__device__ __align__(16) h16 g_h0l[NB * HH];
__device__ __align__(16) h16 g_h1h[NB * HH];
__device__ __align__(16) h16 g_h1l[NB * HH];
__device__ __align__(16) h16 g_xh[(size_t)NB * TT * 512];
__device__ __align__(16) h16 g_xl[(size_t)NB * TT * 512];
__device__ __align__(16) h16 g_W0[(size_t)G3 * K0];   // [Wx0|Wh0], rows [i|g|o]
__device__ __align__(16) h16 g_W1[(size_t)G3 * K1];   // [Wx1|Wh1]

// ---------------- helpers ----------------
__device__ __forceinline__ float sigmoid_(float x) { return 1.0f / (1.0f + expf(-x)); }
__device__ __forceinline__ float tanh_(float x) { return 1.0f - 2.0f / (expf(2.0f * x) + 1.0f); }

__device__ __forceinline__ uint32_t smem_u32(const void* p) {
    uint32_t a;
    asm("{ .reg .u64 t; cvta.to.shared.u64 t, %1; cvt.u32.u64 %0, t; }" : "=r"(a) : "l"(p));
    return a;
}
#define SWZ(x) ((x) ^ (((x) >> 3) & 0x70))

__device__ __forceinline__ void cp16(uint32_t dst, const void* src) {
    asm volatile("cp.async.cg.shared.global [%0], [%1], 16;" :: "r"(dst), "l"(src));
}
#define CP_COMMIT() asm volatile("cp.async.commit_group;" ::: "memory")

#define LDSM4(r, addr) \
    asm volatile("ldmatrix.sync.aligned.m8n8.x4.shared.b16 {%0,%1,%2,%3}, [%4];" \
        : "=r"((r)[0]), "=r"((r)[1]), "=r"((r)[2]), "=r"((r)[3]) : "r"(addr))

#define MMA(c, a, b0, b1) \
    asm volatile("mma.sync.aligned.m16n8k16.row.col.f32.f16.f16.f32 " \
        "{%0,%1,%2,%3},{%4,%5,%6,%7},{%8,%9},{%0,%1,%2,%3};" \
        : "+f"((c)[0]), "+f"((c)[1]), "+f"((c)[2]), "+f"((c)[3]) \
        : "r"((a)[0]), "r"((a)[1]), "r"((a)[2]), "r"((a)[3]), "r"(b0), "r"(b1))

// sense-reversing grid barrier (bounded state -> replay-consistent)
__device__ __forceinline__ void grid_sync(int& sense) {
    sense ^= 1;
    __syncthreads();
    if (threadIdx.x == 0) {
        __threadfence();
        unsigned old = atomicAdd(&g_count, 1u);
        if (old == GRID - 1) {
            g_count = 0;
            asm volatile("st.global.release.gpu.u32 [%0], %1;"
                         :: "l"(&g_sense), "r"((unsigned)sense));
        } else {
            unsigned v;
            do {
                asm volatile("ld.global.acquire.gpu.u32 %0, [%1];"
                             : "=r"(v) : "l"(&g_sense));
            } while (v != (unsigned)sense);
        }
    }
    __syncthreads();
}

// ---------------- init / convert ----------------
__global__ void init_state() {
    int i = blockIdx.x * blockDim.x + threadIdx.x;
    if (i == 0) { g_count = 0u; g_sense = 0u; }
    if (i < NB * HH) {
        g_c0[i] = 0.f; g_c1[i] = 0.f;
        h16 z = __float2half(0.f);
        g_h0h[i] = z; g_h0l[i] = z; g_h1h[i] = z; g_h1l[i] = z;
    }
}

#define NW0E ((size_t)G3 * K0)
#define NW1E ((size_t)G3 * K1)
#define NXE  ((size_t)NB * TT * 512)

__global__ void convert_all(const float* __restrict__ x,
    const float* __restrict__ Wx0, const float* __restrict__ Wh0,
    const float* __restrict__ Wx1, const float* __restrict__ Wh1)
{
    size_t idx = (size_t)blockIdx.x * 256 + threadIdx.x;
    if (idx < NW0E) {
        int r = (int)(idx / K0), k = (int)(idx % K0);
        int R = r + (r >= HH ? HH : 0);        // packed [i|g|o] -> orig [i,f,g,o]
        float v = (k < 512) ? Wx0[(size_t)R * 512 + k] : Wh0[(size_t)R * HH + (k - 512)];
        g_W0[idx] = __float2half(v);
    } else if (idx < NW0E + NW1E) {
        size_t i2 = idx - NW0E;
        int r = (int)(i2 / K1), k = (int)(i2 % K1);
        int R = r + (r >= HH ? HH : 0);
        float v = (k < HH) ? Wx1[(size_t)R * HH + k] : Wh1[(size_t)R * HH + (k - HH)];
        g_W1[i2] = __float2half(v);
    } else {
        size_t i2 = idx - NW0E - NW1E;
        if (i2 >= NXE) return;
        float v = x[i2];
        h16 h = __float2half(v);
        g_xh[i2] = h;
        g_xl[i2] = __float2half(v - __half2float(h));
    }
}

// ---------------- smem tile loads (512 threads) ----------------
// W slot: 128 rows x 64 halfs (128B/row), SW128 swizzled, 16KB
__device__ __forceinline__ void load_Wslot(uint32_t sbase,
    const h16* __restrict__ W, int k0, int ws, int tid)
{
#pragma unroll
    for (int i = 0; i < 2; i++) {
        int seg = tid + i * NTHREADS;          // 0..1023
        int row = seg >> 3, sc = seg & 7;
        uint32_t so = SWZ((uint32_t)(row * 128 + sc * 16));
        cp16(sbase + so, W + (size_t)row * ws + k0 + sc * 8);
    }
}
// B stage: Bh (64x64 halfs, 8KB) at +0, Bl at +8192
__device__ __forceinline__ void load_Bstage(uint32_t sbase,
    const h16* __restrict__ Bh, const h16* __restrict__ Bl, int k0, int bs, int tid)
{
#pragma unroll
    for (int i = 0; i < 2; i++) {
        int seg = tid + i * NTHREADS;          // 0..1023: first 512 Bh, next 512 Bl
        int row = (seg & 511) >> 3, sc = seg & 7;
        uint32_t so = SWZ((uint32_t)(row * 128 + sc * 16)) + (seg < 512 ? 0u : 8192u);
        const h16* src = (seg < 512 ? Bh : Bl) + (size_t)row * bs + k0 + sc * 8;
        cp16(sbase + so, src);
    }
}

// B source per chunk. L0: c<8 -> x(t), else h0. L1: c<16 -> h0, else h1.
template <int LAYER>
__device__ __forceinline__ void getB(int c, int t,
    const h16*& Bh, const h16*& Bl, int& bk0, int& bs)
{
    if (LAYER == 0) {
        if (c < 8) { Bh = g_xh + (size_t)t * 512; Bl = g_xl + (size_t)t * 512;
                     bs = TT * 512; bk0 = c * 64; }
        else       { Bh = g_h0h; Bl = g_h0l; bs = HH; bk0 = (c - 8) * 64; }
    } else {
        if (c < 16) { Bh = g_h0h; Bl = g_h0l; bs = HH; bk0 = c * 64; }
        else        { Bh = g_h1h; Bl = g_h1l; bs = HH; bk0 = (c - 16) * 64; }
    }
}

// ---------------- warp MMA: 16 warps (4M x 4N), 2-term fp16 ----------------
__device__ __forceinline__ void compute_chunk(uint32_t wslot, uint32_t bstage,
    float acc[2][2][4], int lane, int warpM, int warpN)
{
#pragma unroll
    for (int kk = 0; kk < 4; kk++) {
        const int kByte = kk * 32;
        uint32_t ah[2][4];
#pragma unroll
        for (int mt = 0; mt < 2; mt++) {
            int row = warpM * 32 + mt * 16 + (lane & 7) + ((lane >> 3) & 1) * 8;
            int col = kByte + ((lane >> 4) << 4);
            LDSM4(ah[mt], wslot + SWZ((uint32_t)(row * 128 + col)));
        }
        uint32_t bh[4], bl[4];
        {
            int row = warpN * 16 + (lane & 7) + ((lane >> 4) & 1) * 8;
            int col = kByte + (((lane >> 3) & 1) << 4);
            uint32_t a = SWZ((uint32_t)(row * 128 + col));
            LDSM4(bh, bstage + a);
            LDSM4(bl, bstage + 8192 + a);
        }
#pragma unroll
        for (int mt = 0; mt < 2; mt++)
#pragma unroll
            for (int nt = 0; nt < 2; nt++) {
                MMA(acc[mt][nt], ah[mt], bh[nt * 2], bh[nt * 2 + 1]);
                MMA(acc[mt][nt], ah[mt], bl[nt * 2], bl[nt * 2 + 1]);
            }
    }
}

// ---------------- gemm phase (W resident in smem; B pipelined) ----------------
template <int LAYER>
__device__ __forceinline__ void gemm_phase(uint32_t smem, float* __restrict__ part,
                                           int pf, int t)
{
    const int ct = blockIdx.x / SPLITS, sp = blockIdx.x % SPLITS;
    const int col0 = ct * 128;
    const int CH = (LAYER == 0) ? CH0 : CH1;
    const int lo = (sp * CH) / SPLITS, hi = ((sp + 1) * CH) / SPLITS;
    const int NC = hi - lo;
    const int tid = threadIdx.x;
    const int lane = tid & 31, wid = tid >> 5;
    const int warpM = wid & 3, warpN = wid >> 2;
    const uint32_t wbase = smem + (LAYER == 0 ? W0_OFF : W1_OFF);

    float acc[2][2][4];
#pragma unroll
    for (int i = 0; i < 2; i++)
#pragma unroll
        for (int j = 0; j < 2; j++)
#pragma unroll
            for (int k = 0; k < 4; k++) acc[i][j][k] = 0.f;

    auto ldB = [&](int cl) {
        const h16 *Bh, *Bl; int bk0, bs;
        getB<LAYER>(lo + cl, t, Bh, Bl, bk0, bs);
        load_Bstage(smem + B_OFF + (cl % 3) * B_STAGE, Bh, Bl, bk0, bs, tid);
        CP_COMMIT();
    };
    if (pf) { CP_COMMIT(); } else { ldB(0); }   // pf: chunk0 B prefetched earlier
    if (NC > 1) ldB(1);
    for (int c = 0; c < NC; c++) {
        if (c + 1 < NC) { asm volatile("cp.async.wait_group 1;" ::: "memory"); }
        else            { asm volatile("cp.async.wait_group 0;" ::: "memory"); }
        __syncthreads();
        if (c + 2 < NC) ldB(c + 2);
        compute_chunk(wbase + (uint32_t)c * 16384,
                      smem + B_OFF + (c % 3) * B_STAGE, acc, lane, warpM, warpN);
    }
    __syncthreads();   // B stages idle; safe for cross-phase prefetch

    const int g = lane >> 2, tig = lane & 3;
#pragma unroll
    for (int mt = 0; mt < 2; mt++) {
        int colA = col0 + warpM * 32 + mt * 16 + g;
#pragma unroll
        for (int nt = 0; nt < 2; nt++) {
            int b = warpN * 16 + nt * 8 + tig * 2;
            float* p0 = part + ((size_t)sp * NB + b) * G3;
            p0[colA] = acc[mt][nt][0];
            p0[G3 + colA] = acc[mt][nt][1];
            p0[colA + 8] = acc[mt][nt][2];
            p0[G3 + colA + 8] = acc[mt][nt][3];
        }
    }
}

// prefetch B of first chunk of phase LAYER into stage 0 (no commit)
template <int LAYER>
__device__ __forceinline__ void prefetchB(uint32_t smem, int t) {
    const int sp = blockIdx.x % SPLITS;
    const int CH = (LAYER == 0) ? CH0 : CH1;
    const int lo = (sp * CH) / SPLITS;
    const h16 *Bh, *Bl; int bk0, bs;
    getB<LAYER>(lo, t, Bh, Bl, bk0, bs);
    load_Bstage(smem + B_OFF, Bh, Bl, bk0, bs, threadIdx.x);
}

// ---------------- pointwise ----------------
template <int LAYER>
__device__ __forceinline__ void pointwise(const float* __restrict__ part,
    const float* __restrict__ bias, const float* __restrict__ Wc,
    float* __restrict__ out, int t)
{
    int cell = blockIdx.x * NTHREADS + threadIdx.x;
    if (cell >= NB * HH) return;
    int b = cell >> 10, j = cell & (HH - 1);
    float si = 0.f, sg = 0.f, so = 0.f;
#pragma unroll
    for (int sp = 0; sp < SPLITS; sp++) {
        const float* p = part + ((size_t)sp * NB + b) * G3 + j;
        si += p[0]; sg += p[HH]; so += p[2 * HH];
    }
    float pi = si + bias[j];
    float pg = sg + bias[2 * HH + j];
    float po = so + bias[3 * HH + j];
    float* cb = (LAYER == 0) ? g_c0 : g_c1;
    float c = cb[cell];
    float ig = sigmoid_(pi + Wc[j] * c);
    float gg = tanh_(pg);
    float og = sigmoid_(po + Wc[2 * HH + j] * c);
    float cn = gg * (c + ig);      // faithful: forget gate unused
    float hn = og * tanh_(c);      // faithful: uses OLD cell state
    cb[cell] = cn;
    h16 hh = __float2half(hn);
    h16 hl = __float2half(hn - __half2float(hh));
    if (LAYER == 0) {
        g_h0h[cell] = hh; g_h0l[cell] = hl;
    } else {
        g_h1h[cell] = hh; g_h1l[cell] = hl;
        out[((size_t)b * TT + t) * HH + j] = hn;
        if (t == TT - 1) {
            out[(size_t)NB * TT * HH + cell] = hn;
            out[(size_t)NB * TT * HH + NB * HH + cell] = cn;
        }
    }
}

__global__ __launch_bounds__(NTHREADS, 1) void lstm_persistent(
    const float* __restrict__ b0, const float* __restrict__ b1,
    const float* __restrict__ Wc0, const float* __restrict__ Wc1,
    float* __restrict__ out)
{
    extern __shared__ char smem_raw[];
    uint32_t smem = smem_u32(smem_raw);
    const int ct = blockIdx.x / SPLITS, sp = blockIdx.x % SPLITS;
    const int col0 = ct * 128;
    const int lo0 = (sp * CH0) / SPLITS;
    const int lo1 = (sp * CH1) / SPLITS, hi1 = ((sp + 1) * CH1) / SPLITS;
    const int tid = threadIdx.x;

    // ---- one-time: load this CTA's W slices into smem (resident all 256 steps)
#pragma unroll
    for (int s = 0; s < 4; s++)
        load_Wslot(smem + W0_OFF + s * 16384, g_W0 + (size_t)col0 * K0,
                   (lo0 + s) * 64, K0, tid);
    for (int s = 0; s < hi1 - lo1; s++)
        load_Wslot(smem + W1_OFF + s * 16384, g_W1 + (size_t)col0 * K1,
                   (lo1 + s) * 64, K1, tid);
    CP_COMMIT();
    asm volatile("cp.async.wait_group 0;" ::: "memory");
    __syncthreads();

    const int pf1 = (lo1 >= 16) ? 1 : 0;       // gemm1 chunk0 reads h1 -> prefetchable
    int sense = 0;
    int pf0 = 0;
    for (int t = 0; t < TT; t++) {
        gemm_phase<0>(smem, g_part0, pf0, t);    // gates0 = [x_t|h0(t-1)] . W0^T
        if (pf1) prefetchB<1>(smem, t);          // B=h1(t-1), final since pw1(t-1)
        grid_sync(sense);
        pointwise<0>(g_part0, b0, Wc0, out, t);  // writes h0(t)
        grid_sync(sense);
        gemm_phase<1>(smem, g_part1, pf1, t);    // gates1 = [h0(t)|h1(t-1)] . W1^T
        if (t + 1 < TT) {
            prefetchB<0>(smem, t + 1);           // B = x(t+1) or h0(t): both final
            pf0 = 1;
        }
        grid_sync(sense);
        pointwise<1>(g_part1, b1, Wc1, out, t);  // writes h1(t), out
        // pw<1>(t) ordered before gemm<1>(t+1)'s h1/part1 reads by syncs of t+1
    }
}

// ---------------- host launch ----------------
extern "C" void kernel_launch(void* const* d_in, const int* in_sizes, int n_in,
                              void* d_out, int out_size) {
    const float* x   = (const float*)d_in[0];
    const float* Wx0 = (const float*)d_in[1];
    const float* Wh0 = (const float*)d_in[2];
    const float* b0  = (const float*)d_in[3];
    const float* Wc0 = (const float*)d_in[4];
    const float* Wx1 = (const float*)d_in[5];
    const float* Wh1 = (const float*)d_in[6];
    const float* b1  = (const float*)d_in[7];
    const float* Wc1 = (const float*)d_in[8];
    float* out = (float*)d_out;

    cudaFuncSetAttribute(lstm_persistent,
                         cudaFuncAttributeMaxDynamicSharedMemorySize, SMEM_TOTAL);

    size_t total_conv = NW0E + NW1E + NXE;
    int conv_blocks = (int)((total_conv + 255) / 256);

    init_state<<<256, 256>>>();
    convert_all<<<conv_blocks, 256>>>(x, Wx0, Wh0, Wx1, Wh1);
    lstm_persistent<<<GRID, NTHREADS, SMEM_TOTAL>>>(b0, b1, Wc0, Wc1, out);
}

// round 11
// speedup vs baseline: 1.3972x; 1.1062x over previous
#include <cuda_runtime.h>
#include <cuda_fp16.h>
#include <math.h>
#include <stdint.h>

#define NB 64
#define TT 256
#define HH 1024
#define G3 3072
#define GRID 144
#define SPLITS 6
#define NTHREADS 512
#define K0 1536
#define K1 2048
#define CH0 24
#define CH1 32
#define W0_OFF 0
#define W1_OFF 65536
#define B_OFF 163840
#define B_STAGE 16384
#define SMEM_TOTAL 212992

typedef __half h16;

// ---------------- static device scratch ----------------
__device__ float g_c0[NB * HH];
__device__ float g_c1[NB * HH];
__device__ float g_part0[(size_t)SPLITS * NB * G3];
__device__ float g_part1[(size_t)SPLITS * NB * G3];
__device__ unsigned g_count, g_sense;

__device__ __align__(16) h16 g_h0h[NB * HH];
__device__ __align__(16) h16 g_h0l[NB * HH];
__device__ __align__(16) h16 g_h1h[NB * HH];
__device__ __align__(16) h16 g_h1l[NB * HH];
__device__ __align__(16) h16 g_xh[(size_t)NB * TT * 512];
__device__ __align__(16) h16 g_xl[(size_t)NB * TT * 512];
__device__ __align__(16) h16 g_W0[(size_t)G3 * K0];   // [Wx0|Wh0], rows [i|g|o]
__device__ __align__(16) h16 g_W1[(size_t)G3 * K1];   // [Wx1|Wh1]

// ---------------- helpers ----------------
__device__ __forceinline__ float sigmoid_(float x) { return 1.0f / (1.0f + expf(-x)); }
__device__ __forceinline__ float tanh_(float x) { return 1.0f - 2.0f / (expf(2.0f * x) + 1.0f); }

__device__ __forceinline__ uint32_t smem_u32(const void* p) {
    uint32_t a;
    asm("{ .reg .u64 t; cvta.to.shared.u64 t, %1; cvt.u32.u64 %0, t; }" : "=r"(a) : "l"(p));
    return a;
}
#define SWZ(x) ((x) ^ (((x) >> 3) & 0x70))

__device__ __forceinline__ void cp16(uint32_t dst, const void* src) {
    asm volatile("cp.async.cg.shared.global [%0], [%1], 16;" :: "r"(dst), "l"(src));
}
#define CP_COMMIT() asm volatile("cp.async.commit_group;" ::: "memory")

#define LDSM4(r, addr) \
    asm volatile("ldmatrix.sync.aligned.m8n8.x4.shared.b16 {%0,%1,%2,%3}, [%4];" \
        : "=r"((r)[0]), "=r"((r)[1]), "=r"((r)[2]), "=r"((r)[3]) : "r"(addr))

#define MMA(c, a, b0, b1) \
    asm volatile("mma.sync.aligned.m16n8k16.row.col.f32.f16.f16.f32 " \
        "{%0,%1,%2,%3},{%4,%5,%6,%7},{%8,%9},{%0,%1,%2,%3};" \
        : "+f"((c)[0]), "+f"((c)[1]), "+f"((c)[2]), "+f"((c)[3]) \
        : "r"((a)[0]), "r"((a)[1]), "r"((a)[2]), "r"((a)[3]), "r"(b0), "r"(b1))

// sense-reversing grid barrier (bounded state -> replay-consistent)
__device__ __forceinline__ void grid_sync(int& sense) {
    sense ^= 1;
    __syncthreads();
    if (threadIdx.x == 0) {
        __threadfence();
        unsigned old = atomicAdd(&g_count, 1u);
        if (old == GRID - 1) {
            g_count = 0;
            asm volatile("st.global.release.gpu.u32 [%0], %1;"
                         :: "l"(&g_sense), "r"((unsigned)sense));
        } else {
            unsigned v;
            do {
                asm volatile("ld.global.acquire.gpu.u32 %0, [%1];"
                             : "=r"(v) : "l"(&g_sense));
            } while (v != (unsigned)sense);
        }
    }
    __syncthreads();
}

// ---------------- init / convert ----------------
__global__ void init_state() {
    int i = blockIdx.x * blockDim.x + threadIdx.x;
    if (i == 0) { g_count = 0u; g_sense = 0u; }
    if (i < NB * HH) {
        g_c0[i] = 0.f; g_c1[i] = 0.f;
        h16 z = __float2half(0.f);
        g_h0h[i] = z; g_h0l[i] = z; g_h1h[i] = z; g_h1l[i] = z;
    }
}

#define NW0E ((size_t)G3 * K0)
#define NW1E ((size_t)G3 * K1)
#define NXE  ((size_t)NB * TT * 512)

__global__ void convert_all(const float* __restrict__ x,
    const float* __restrict__ Wx0, const float* __restrict__ Wh0,
    const float* __restrict__ Wx1, const float* __restrict__ Wh1)
{
    size_t idx = (size_t)blockIdx.x * 256 + threadIdx.x;
    if (idx < NW0E) {
        int r = (int)(idx / K0), k = (int)(idx % K0);
        int R = r + (r >= HH ? HH : 0);        // packed [i|g|o] -> orig [i,f,g,o]
        float v = (k < 512) ? Wx0[(size_t)R * 512 + k] : Wh0[(size_t)R * HH + (k - 512)];
        g_W0[idx] = __float2half(v);
    } else if (idx < NW0E + NW1E) {
        size_t i2 = idx - NW0E;
        int r = (int)(i2 / K1), k = (int)(i2 % K1);
        int R = r + (r >= HH ? HH : 0);
        float v = (k < HH) ? Wx1[(size_t)R * HH + k] : Wh1[(size_t)R * HH + (k - HH)];
        g_W1[i2] = __float2half(v);
    } else {
        size_t i2 = idx - NW0E - NW1E;
        if (i2 >= NXE) return;
        float v = x[i2];
        h16 h = __float2half(v);
        g_xh[i2] = h;
        g_xl[i2] = __float2half(v - __half2float(h));
    }
}

// ---------------- smem tile loads (512 threads) ----------------
__device__ __forceinline__ void load_Wslot(uint32_t sbase,
    const h16* __restrict__ W, int k0, int ws, int tid)
{
#pragma unroll
    for (int i = 0; i < 2; i++) {
        int seg = tid + i * NTHREADS;          // 0..1023
        int row = seg >> 3, sc = seg & 7;
        uint32_t so = SWZ((uint32_t)(row * 128 + sc * 16));
        cp16(sbase + so, W + (size_t)row * ws + k0 + sc * 8);
    }
}
__device__ __forceinline__ void load_Bstage(uint32_t sbase,
    const h16* __restrict__ Bh, const h16* __restrict__ Bl, int k0, int bs, int tid)
{
#pragma unroll
    for (int i = 0; i < 2; i++) {
        int seg = tid + i * NTHREADS;          // first 512 Bh, next 512 Bl
        int row = (seg & 511) >> 3, sc = seg & 7;
        uint32_t so = SWZ((uint32_t)(row * 128 + sc * 16)) + (seg < 512 ? 0u : 8192u);
        const h16* src = (seg < 512 ? Bh : Bl) + (size_t)row * bs + k0 + sc * 8;
        cp16(sbase + so, src);
    }
}

// B source per chunk. L0: c<8 -> x(t), else h0. L1: c<16 -> h0, else h1.
template <int LAYER>
__device__ __forceinline__ void getB(int c, int t,
    const h16*& Bh, const h16*& Bl, int& bk0, int& bs)
{
    if (LAYER == 0) {
        if (c < 8) { Bh = g_xh + (size_t)t * 512; Bl = g_xl + (size_t)t * 512;
                     bs = TT * 512; bk0 = c * 64; }
        else       { Bh = g_h0h; Bl = g_h0l; bs = HH; bk0 = (c - 8) * 64; }
    } else {
        if (c < 16) { Bh = g_h0h; Bl = g_h0l; bs = HH; bk0 = c * 64; }
        else        { Bh = g_h1h; Bl = g_h1l; bs = HH; bk0 = (c - 16) * 64; }
    }
}

// ---------------- warp MMA: 16 warps (4M x 4N), 2-term fp16 ----------------
__device__ __forceinline__ void compute_chunk(uint32_t wslot, uint32_t bstage,
    float acc[2][2][4], int lane, int warpM, int warpN)
{
#pragma unroll
    for (int kk = 0; kk < 4; kk++) {
        const int kByte = kk * 32;
        uint32_t ah[2][4];
#pragma unroll
        for (int mt = 0; mt < 2; mt++) {
            int row = warpM * 32 + mt * 16 + (lane & 7) + ((lane >> 3) & 1) * 8;
            int col = kByte + ((lane >> 4) << 4);
            LDSM4(ah[mt], wslot + SWZ((uint32_t)(row * 128 + col)));
        }
        uint32_t bh[4], bl[4];
        {
            int row = warpN * 16 + (lane & 7) + ((lane >> 4) & 1) * 8;
            int col = kByte + (((lane >> 3) & 1) << 4);
            uint32_t a = SWZ((uint32_t)(row * 128 + col));
            LDSM4(bh, bstage + a);
            LDSM4(bl, bstage + 8192 + a);
        }
#pragma unroll
        for (int mt = 0; mt < 2; mt++)
#pragma unroll
            for (int nt = 0; nt < 2; nt++) {
                MMA(acc[mt][nt], ah[mt], bh[nt * 2], bh[nt * 2 + 1]);
                MMA(acc[mt][nt], ah[mt], bl[nt * 2], bl[nt * 2 + 1]);
            }
    }
}

// ---------------- gemm phase (W resident in smem; B pipelined) ----------------
template <int LAYER>
__device__ __forceinline__ void gemm_phase(uint32_t smem, float* __restrict__ part, int t)
{
    const int ct = blockIdx.x / SPLITS, sp = blockIdx.x % SPLITS;
    const int col0 = ct * 128;
    const int CH = (LAYER == 0) ? CH0 : CH1;
    const int lo = (sp * CH) / SPLITS, hi = ((sp + 1) * CH) / SPLITS;
    const int NC = hi - lo;
    const int tid = threadIdx.x;
    const int lane = tid & 31, wid = tid >> 5;
    const int warpM = wid & 3, warpN = wid >> 2;
    const uint32_t wbase = smem + (LAYER == 0 ? W0_OFF : W1_OFF);

    float acc[2][2][4];
#pragma unroll
    for (int i = 0; i < 2; i++)
#pragma unroll
        for (int j = 0; j < 2; j++)
#pragma unroll
            for (int k = 0; k < 4; k++) acc[i][j][k] = 0.f;

    auto ldB = [&](int cl) {
        const h16 *Bh, *Bl; int bk0, bs;
        getB<LAYER>(lo + cl, t, Bh, Bl, bk0, bs);
        load_Bstage(smem + B_OFF + (cl % 3) * B_STAGE, Bh, Bl, bk0, bs, tid);
        CP_COMMIT();
    };
    ldB(0);
    if (NC > 1) ldB(1);
    for (int c = 0; c < NC; c++) {
        if (c + 1 < NC) { asm volatile("cp.async.wait_group 1;" ::: "memory"); }
        else            { asm volatile("cp.async.wait_group 0;" ::: "memory"); }
        __syncthreads();
        if (c + 2 < NC) ldB(c + 2);
        // W slots for this phase are packed from local slot 0: slot c <-> chunk lo+c
        compute_chunk(wbase + (uint32_t)c * 16384,
                      smem + B_OFF + (c % 3) * B_STAGE, acc, lane, warpM, warpN);
    }
    __syncthreads();   // B stages idle before next phase reuses them

    const int g = lane >> 2, tig = lane & 3;
#pragma unroll
    for (int mt = 0; mt < 2; mt++) {
        int colA = col0 + warpM * 32 + mt * 16 + g;
#pragma unroll
        for (int nt = 0; nt < 2; nt++) {
            int b = warpN * 16 + nt * 8 + tig * 2;
            float* p0 = part + ((size_t)sp * NB + b) * G3;
            p0[colA] = acc[mt][nt][0];
            p0[G3 + colA] = acc[mt][nt][1];
            p0[colA + 8] = acc[mt][nt][2];
            p0[G3 + colA + 8] = acc[mt][nt][3];
        }
    }
}

// ---------------- pointwise (one layer, one cell per thread) ----------------
__device__ __forceinline__ void pw_layer(const float* __restrict__ part,
    const float* __restrict__ bias, const float* __restrict__ Wc,
    float* __restrict__ cb, h16* __restrict__ hh_buf, h16* __restrict__ hl_buf,
    float* __restrict__ out, int t, bool isL1, int cell)
{
    int b = cell >> 10, j = cell & (HH - 1);
    float si = 0.f, sg = 0.f, so = 0.f;
#pragma unroll
    for (int sp = 0; sp < SPLITS; sp++) {
        const float* p = part + ((size_t)sp * NB + b) * G3 + j;
        si += p[0]; sg += p[HH]; so += p[2 * HH];
    }
    float pi = si + bias[j];
    float pg = sg + bias[2 * HH + j];
    float po = so + bias[3 * HH + j];
    float c = cb[cell];
    float ig = sigmoid_(pi + Wc[j] * c);
    float gg = tanh_(pg);
    float og = sigmoid_(po + Wc[2 * HH + j] * c);
    float cn = gg * (c + ig);      // faithful: forget gate unused
    float hn = og * tanh_(c);      // faithful: uses OLD cell state
    cb[cell] = cn;
    h16 hh = __float2half(hn);
    hh_buf[cell] = hh;
    hl_buf[cell] = __float2half(hn - __half2float(hh));
    if (isL1) {
        out[((size_t)b * TT + t) * HH + j] = hn;
        if (t == TT - 1) {
            out[(size_t)NB * TT * HH + cell] = hn;
            out[(size_t)NB * TT * HH + NB * HH + cell] = cn;
        }
    }
}

__global__ __launch_bounds__(NTHREADS, 1) void lstm_persistent(
    const float* __restrict__ b0, const float* __restrict__ b1,
    const float* __restrict__ Wc0, const float* __restrict__ Wc1,
    float* __restrict__ out)
{
    extern __shared__ char smem_raw[];
    uint32_t smem = smem_u32(smem_raw);
    const int ct = blockIdx.x / SPLITS, sp = blockIdx.x % SPLITS;
    const int col0 = ct * 128;
    const int lo0 = (sp * CH0) / SPLITS;
    const int lo1 = (sp * CH1) / SPLITS, hi1 = ((sp + 1) * CH1) / SPLITS;
    const int tid = threadIdx.x;
    const int cell = blockIdx.x * NTHREADS + tid;
    const bool hasCell = (cell < NB * HH);

    // one-time: load this CTA's W slices into smem (resident all 256 steps)
#pragma unroll
    for (int s = 0; s < 4; s++)
        load_Wslot(smem + W0_OFF + s * 16384, g_W0 + (size_t)col0 * K0,
                   (lo0 + s) * 64, K0, tid);
    for (int s = 0; s < hi1 - lo1; s++)
        load_Wslot(smem + W1_OFF + s * 16384, g_W1 + (size_t)col0 * K1,
                   (lo1 + s) * 64, K1, tid);
    CP_COMMIT();
    asm volatile("cp.async.wait_group 0;" ::: "memory");
    __syncthreads();

    int sense = 0;
    // ---- prologue: h0(0)
    gemm_phase<0>(smem, g_part0, 0);
    grid_sync(sense);
    if (hasCell) pw_layer(g_part0, b0, Wc0, g_c0, g_h0h, g_h0l, out, 0, false, cell);
    grid_sync(sense);

    // ---- steady state: 2 syncs / step
    for (int t = 0; t < TT; t++) {
        gemm_phase<1>(smem, g_part1, t);            // [h0(t)|h1(t-1)] . W1^T
        if (t + 1 < TT) gemm_phase<0>(smem, g_part0, t + 1);  // [x(t+1)|h0(t)] . W0^T
        grid_sync(sense);
        if (hasCell) {
            pw_layer(g_part1, b1, Wc1, g_c1, g_h1h, g_h1l, out, t, true, cell);
            if (t + 1 < TT)
                pw_layer(g_part0, b0, Wc0, g_c0, g_h0h, g_h0l, out, t + 1, false, cell);
        }
        grid_sync(sense);
    }
}

// ---------------- host launch ----------------
extern "C" void kernel_launch(void* const* d_in, const int* in_sizes, int n_in,
                              void* d_out, int out_size) {
    const float* x   = (const float*)d_in[0];
    const float* Wx0 = (const float*)d_in[1];
    const float* Wh0 = (const float*)d_in[2];
    const float* b0  = (const float*)d_in[3];
    const float* Wc0 = (const float*)d_in[4];
    const float* Wx1 = (const float*)d_in[5];
    const float* Wh1 = (const float*)d_in[6];
    const float* b1  = (const float*)d_in[7];
    const float* Wc1 = (const float*)d_in[8];
    float* out = (float*)d_out;

    cudaFuncSetAttribute(lstm_persistent,
                         cudaFuncAttributeMaxDynamicSharedMemorySize, SMEM_TOTAL);

    size_t total_conv = NW0E + NW1E + NXE;
    int conv_blocks = (int)((total_conv + 255) / 256);

    init_state<<<256, 256>>>();
    convert_all<<<conv_blocks, 256>>>(x, Wx0, Wh0, Wx1, Wh1);
    lstm_persistent<<<GRID, NTHREADS, SMEM_TOTAL>>>(b0, b1, Wc0, Wc1, out);
}

// round 12
// speedup vs baseline: 1.4891x; 1.0658x over previous
#include <cuda_runtime.h>
#include <cuda_fp16.h>
#include <math.h>
#include <stdint.h>

#define NB 64
#define TT 256
#define HH 1024
#define G3 3072
#define GRID 144
#define SPLITS 6
#define NTHREADS 512
#define K0 1536
#define K1 2048
#define CH1 32
#define W0_OFF 0
#define W1_OFF 65536
#define B_OFF 163840
#define B_STAGE 16384
#define SMEM_TOTAL 212992

typedef __half h16;

// ---------------- static device scratch ----------------
__device__ float g_c0[NB * HH];
__device__ float g_c1[NB * HH];
__device__ float g_part0[(size_t)SPLITS * NB * G3];
__device__ float g_part1[(size_t)SPLITS * NB * G3];
__device__ unsigned g_count, g_sense;     // full barrier
__device__ unsigned g_count2, g_sense2;   // deferred barrier

__device__ __align__(16) h16 g_h0h[NB * HH];
__device__ __align__(16) h16 g_h0l[NB * HH];
__device__ __align__(16) h16 g_h1h[NB * HH];
__device__ __align__(16) h16 g_h1l[NB * HH];
__device__ __align__(16) h16 g_xh[(size_t)NB * TT * 512];
__device__ __align__(16) h16 g_xl[(size_t)NB * TT * 512];
__device__ __align__(16) h16 g_W0[(size_t)G3 * K0];   // [Wx0|Wh0], rows [i|g|o]
__device__ __align__(16) h16 g_W1[(size_t)G3 * K1];   // [Wx1|Wh1]

// ---------------- helpers ----------------
__device__ __forceinline__ float sigmoid_(float x) {
    return __fdividef(1.0f, 1.0f + __expf(-x));
}
__device__ __forceinline__ float tanh_(float x) {
    return 1.0f - __fdividef(2.0f, __expf(2.0f * x) + 1.0f);
}

__device__ __forceinline__ uint32_t smem_u32(const void* p) {
    uint32_t a;
    asm("{ .reg .u64 t; cvta.to.shared.u64 t, %1; cvt.u32.u64 %0, t; }" : "=r"(a) : "l"(p));
    return a;
}
#define SWZ(x) ((x) ^ (((x) >> 3) & 0x70))

__device__ __forceinline__ void cp16(uint32_t dst, const void* src) {
    asm volatile("cp.async.cg.shared.global [%0], [%1], 16;" :: "r"(dst), "l"(src));
}
#define CP_COMMIT() asm volatile("cp.async.commit_group;" ::: "memory")

#define LDSM4(r, addr) \
    asm volatile("ldmatrix.sync.aligned.m8n8.x4.shared.b16 {%0,%1,%2,%3}, [%4];" \
        : "=r"((r)[0]), "=r"((r)[1]), "=r"((r)[2]), "=r"((r)[3]) : "r"(addr))

#define MMA(c, a, b0, b1) \
    asm volatile("mma.sync.aligned.m16n8k16.row.col.f32.f16.f16.f32 " \
        "{%0,%1,%2,%3},{%4,%5,%6,%7},{%8,%9},{%0,%1,%2,%3};" \
        : "+f"((c)[0]), "+f"((c)[1]), "+f"((c)[2]), "+f"((c)[3]) \
        : "r"((a)[0]), "r"((a)[1]), "r"((a)[2]), "r"((a)[3]), "r"(b0), "r"(b1))

// full sense-reversing grid barrier
__device__ __forceinline__ void grid_sync(int& sense) {
    sense ^= 1;
    __syncthreads();
    if (threadIdx.x == 0) {
        __threadfence();
        unsigned old = atomicAdd(&g_count, 1u);
        if (old == GRID - 1) {
            g_count = 0;
            asm volatile("st.global.release.gpu.u32 [%0], %1;"
                         :: "l"(&g_sense), "r"((unsigned)sense));
        } else {
            unsigned v;
            do {
                asm volatile("ld.global.acquire.gpu.u32 %0, [%1];"
                             : "=r"(v) : "l"(&g_sense));
            } while (v != (unsigned)sense);
        }
    }
    __syncthreads();
}

// deferred barrier: arrive (non-blocking) / wait (blocking), split in time
__device__ __forceinline__ void dbar_arrive(int& as) {
    as ^= 1;
    __syncthreads();                 // all CTA threads finished pw stores
    if (threadIdx.x == 0) {
        __threadfence();
        unsigned old = atomicAdd(&g_count2, 1u);
        if (old == GRID - 1) {
            g_count2 = 0;
            asm volatile("st.global.release.gpu.u32 [%0], %1;"
                         :: "l"(&g_sense2), "r"((unsigned)as));
        }
    }
}
__device__ __forceinline__ void dbar_wait(int& ws) {
    ws ^= 1;
    if (threadIdx.x == 0) {
        unsigned v;
        do {
            asm volatile("ld.global.acquire.gpu.u32 %0, [%1];"
                         : "=r"(v) : "l"(&g_sense2));
        } while (v != (unsigned)ws);
    }
    __syncthreads();
}

// ---------------- init / convert ----------------
__global__ void init_state() {
    int i = blockIdx.x * blockDim.x + threadIdx.x;
    if (i == 0) { g_count = 0u; g_sense = 0u; g_count2 = 0u; g_sense2 = 0u; }
    if (i < NB * HH) {
        g_c0[i] = 0.f; g_c1[i] = 0.f;
        h16 z = __float2half(0.f);
        g_h0h[i] = z; g_h0l[i] = z; g_h1h[i] = z; g_h1l[i] = z;
    }
}

#define NW0E ((size_t)G3 * K0)
#define NW1E ((size_t)G3 * K1)
#define NXE  ((size_t)NB * TT * 512)

__global__ void convert_all(const float* __restrict__ x,
    const float* __restrict__ Wx0, const float* __restrict__ Wh0,
    const float* __restrict__ Wx1, const float* __restrict__ Wh1)
{
    size_t idx = (size_t)blockIdx.x * 256 + threadIdx.x;
    if (idx < NW0E) {
        int r = (int)(idx / K0), k = (int)(idx % K0);
        int R = r + (r >= HH ? HH : 0);        // packed [i|g|o] -> orig [i,f,g,o]
        float v = (k < 512) ? Wx0[(size_t)R * 512 + k] : Wh0[(size_t)R * HH + (k - 512)];
        g_W0[idx] = __float2half(v);
    } else if (idx < NW0E + NW1E) {
        size_t i2 = idx - NW0E;
        int r = (int)(i2 / K1), k = (int)(i2 % K1);
        int R = r + (r >= HH ? HH : 0);
        float v = (k < HH) ? Wx1[(size_t)R * HH + k] : Wh1[(size_t)R * HH + (k - HH)];
        g_W1[i2] = __float2half(v);
    } else {
        size_t i2 = idx - NW0E - NW1E;
        if (i2 >= NXE) return;
        float v = x[i2];
        h16 h = __float2half(v);
        g_xh[i2] = h;
        g_xl[i2] = __float2half(v - __half2float(h));
    }
}

// ---------------- smem tile loads (512 threads) ----------------
__device__ __forceinline__ void load_Wslot(uint32_t sbase,
    const h16* __restrict__ W, int k0, int ws, int tid)
{
#pragma unroll
    for (int i = 0; i < 2; i++) {
        int seg = tid + i * NTHREADS;          // 0..1023
        int row = seg >> 3, sc = seg & 7;
        uint32_t so = SWZ((uint32_t)(row * 128 + sc * 16));
        cp16(sbase + so, W + (size_t)row * ws + k0 + sc * 8);
    }
}
__device__ __forceinline__ void load_Bstage(uint32_t sbase,
    const h16* __restrict__ Bh, const h16* __restrict__ Bl, int k0, int bs, int tid)
{
#pragma unroll
    for (int i = 0; i < 2; i++) {
        int seg = tid + i * NTHREADS;          // first 512 Bh, next 512 Bl
        int row = (seg & 511) >> 3, sc = seg & 7;
        uint32_t so = SWZ((uint32_t)(row * 128 + sc * 16)) + (seg < 512 ? 0u : 8192u);
        const h16* src = (seg < 512 ? Bh : Bl) + (size_t)row * bs + k0 + sc * 8;
        cp16(sbase + so, src);
    }
}

// B source for a global chunk. L0: c<8 -> x(t) (STATIC), else h0. L1: c<16 -> h0, else h1.
template <int LAYER>
__device__ __forceinline__ void getB(int c, int t,
    const h16*& Bh, const h16*& Bl, int& bk0, int& bs)
{
    if (LAYER == 0) {
        if (c < 8) { Bh = g_xh + (size_t)t * 512; Bl = g_xl + (size_t)t * 512;
                     bs = TT * 512; bk0 = c * 64; }
        else       { Bh = g_h0h; Bl = g_h0l; bs = HH; bk0 = (c - 8) * 64; }
    } else {
        if (c < 16) { Bh = g_h0h; Bl = g_h0l; bs = HH; bk0 = c * 64; }
        else        { Bh = g_h1h; Bl = g_h1l; bs = HH; bk0 = (c - 16) * 64; }
    }
}

// ---------------- warp MMA: 16 warps (4M x 4N), 2-term fp16 ----------------
__device__ __forceinline__ void compute_chunk(uint32_t wslot, uint32_t bstage,
    float acc[2][2][4], int lane, int warpM, int warpN)
{
#pragma unroll
    for (int kk = 0; kk < 4; kk++) {
        const int kByte = kk * 32;
        uint32_t ah[2][4];
#pragma unroll
        for (int mt = 0; mt < 2; mt++) {
            int row = warpM * 32 + mt * 16 + (lane & 7) + ((lane >> 3) & 1) * 8;
            int col = kByte + ((lane >> 4) << 4);
            LDSM4(ah[mt], wslot + SWZ((uint32_t)(row * 128 + col)));
        }
        uint32_t bh[4], bl[4];
        {
            int row = warpN * 16 + (lane & 7) + ((lane >> 4) & 1) * 8;
            int col = kByte + (((lane >> 3) & 1) << 4);
            uint32_t a = SWZ((uint32_t)(row * 128 + col));
            LDSM4(bh, bstage + a);
            LDSM4(bl, bstage + 8192 + a);
        }
#pragma unroll
        for (int mt = 0; mt < 2; mt++)
#pragma unroll
            for (int nt = 0; nt < 2; nt++) {
                MMA(acc[mt][nt], ah[mt], bh[nt * 2], bh[nt * 2 + 1]);
                MMA(acc[mt][nt], ah[mt], bl[nt * 2], bl[nt * 2 + 1]);
            }
    }
}

// slot -> global chunk. gemm0 is round-robin (every split owns 1-2 static x-chunks).
template <int LAYER>
__device__ __forceinline__ int slot_chunk(int sp, int s) {
    return (LAYER == 0) ? (sp + SPLITS * s) : ((sp * CH1) / SPLITS + s);
}

// run pipeline over local W slots [s_begin, s_end), accumulating into acc
template <int LAYER>
__device__ __forceinline__ void gemm_chunks(uint32_t smem, float acc[2][2][4],
                                            int s_begin, int s_end, int sp, int t)
{
    if (s_begin >= s_end) return;
    const int tid = threadIdx.x;
    const int lane = tid & 31, wid = tid >> 5;
    const int warpM = wid & 3, warpN = wid >> 2;
    const uint32_t wbase = smem + (LAYER == 0 ? W0_OFF : W1_OFF);

    auto ldB = [&](int s) {
        const h16 *Bh, *Bl; int bk0, bs;
        getB<LAYER>(slot_chunk<LAYER>(sp, s), t, Bh, Bl, bk0, bs);
        load_Bstage(smem + B_OFF + (s % 3) * B_STAGE, Bh, Bl, bk0, bs, tid);
        CP_COMMIT();
    };
    ldB(s_begin);
    if (s_begin + 1 < s_end) ldB(s_begin + 1);
    for (int s = s_begin; s < s_end; s++) {
        if (s + 1 < s_end) { asm volatile("cp.async.wait_group 1;" ::: "memory"); }
        else               { asm volatile("cp.async.wait_group 0;" ::: "memory"); }
        __syncthreads();
        if (s + 2 < s_end) ldB(s + 2);
        compute_chunk(wbase + (uint32_t)s * 16384,
                      smem + B_OFF + (s % 3) * B_STAGE, acc, lane, warpM, warpN);
    }
    __syncthreads();
}

__device__ __forceinline__ void store_part(float acc[2][2][4], float* __restrict__ part,
                                           int sp, int col0)
{
    const int lane = threadIdx.x & 31, wid = threadIdx.x >> 5;
    const int warpM = wid & 3, warpN = wid >> 2;
    const int g = lane >> 2, tig = lane & 3;
#pragma unroll
    for (int mt = 0; mt < 2; mt++) {
        int colA = col0 + warpM * 32 + mt * 16 + g;
#pragma unroll
        for (int nt = 0; nt < 2; nt++) {
            int b = warpN * 16 + nt * 8 + tig * 2;
            float* p0 = part + ((size_t)sp * NB + b) * G3;
            p0[colA] = acc[mt][nt][0];
            p0[G3 + colA] = acc[mt][nt][1];
            p0[colA + 8] = acc[mt][nt][2];
            p0[G3 + colA + 8] = acc[mt][nt][3];
        }
    }
}

#define ZACC(a) do { \
_Pragma("unroll") for (int _i = 0; _i < 2; _i++) \
_Pragma("unroll") for (int _j = 0; _j < 2; _j++) \
_Pragma("unroll") for (int _k = 0; _k < 4; _k++) (a)[_i][_j][_k] = 0.f; } while (0)

// ---------------- pointwise (one layer, one cell per thread) ----------------
__device__ __forceinline__ void pw_layer(const float* __restrict__ part,
    const float* __restrict__ bias, const float* __restrict__ Wc,
    float* __restrict__ cb, h16* __restrict__ hh_buf, h16* __restrict__ hl_buf,
    float* __restrict__ out, int t, bool isL1, int cell)
{
    int b = cell >> 10, j = cell & (HH - 1);
    float si = 0.f, sg = 0.f, so = 0.f;
#pragma unroll
    for (int sp = 0; sp < SPLITS; sp++) {
        const float* p = part + ((size_t)sp * NB + b) * G3 + j;
        si += p[0]; sg += p[HH]; so += p[2 * HH];
    }
    float pi = si + bias[j];
    float pg = sg + bias[2 * HH + j];
    float po = so + bias[3 * HH + j];
    float c = cb[cell];
    float ig = sigmoid_(pi + Wc[j] * c);
    float gg = tanh_(pg);
    float og = sigmoid_(po + Wc[2 * HH + j] * c);
    float cn = gg * (c + ig);      // faithful: forget gate unused
    float hn = og * tanh_(c);      // faithful: uses OLD cell state
    cb[cell] = cn;
    h16 hh = __float2half(hn);
    hh_buf[cell] = hh;
    hl_buf[cell] = __float2half(hn - __half2float(hh));
    if (isL1) {
        out[((size_t)b * TT + t) * HH + j] = hn;
        if (t == TT - 1) {
            out[(size_t)NB * TT * HH + cell] = hn;
            out[(size_t)NB * TT * HH + NB * HH + cell] = cn;
        }
    }
}

__global__ __launch_bounds__(NTHREADS, 1) void lstm_persistent(
    const float* __restrict__ b0, const float* __restrict__ b1,
    const float* __restrict__ Wc0, const float* __restrict__ Wc1,
    float* __restrict__ out)
{
    extern __shared__ char smem_raw[];
    uint32_t smem = smem_u32(smem_raw);
    const int ct = blockIdx.x / SPLITS, sp = blockIdx.x % SPLITS;
    const int col0 = ct * 128;
    const int lo1 = (sp * CH1) / SPLITS, hi1 = ((sp + 1) * CH1) / SPLITS;
    const int n1 = hi1 - lo1;
    const int nx = (sp < 2) ? 2 : 1;           // static x slots in gemm0 round-robin
    const int tid = threadIdx.x;
    const int cell = blockIdx.x * NTHREADS + tid;
    const bool hasCell = (cell < NB * HH);

    // one-time: resident W slices (gemm0 slots round-robin: chunk sp + 6*s)
#pragma unroll
    for (int s = 0; s < 4; s++)
        load_Wslot(smem + W0_OFF + s * 16384, g_W0 + (size_t)col0 * K0,
                   (sp + SPLITS * s) * 64, K0, tid);
    for (int s = 0; s < n1; s++)
        load_Wslot(smem + W1_OFF + s * 16384, g_W1 + (size_t)col0 * K1,
                   (lo1 + s) * 64, K1, tid);
    CP_COMMIT();
    asm volatile("cp.async.wait_group 0;" ::: "memory");
    __syncthreads();

    int sense = 0, as = 0, ws = 0;
    // ---- prologue: h0(0) (h0/h1 initial zeros already global-visible)
    {
        float acc[2][2][4]; ZACC(acc);
        gemm_chunks<0>(smem, acc, 0, 4, sp, 0);
        store_part(acc, g_part0, sp, col0);
        grid_sync(sense);
        if (hasCell) pw_layer(g_part0, b0, Wc0, g_c0, g_h0h, g_h0l, out, 0, false, cell);
        dbar_arrive(as);
    }

    // ---- steady state: 1 blocking sync + 1 hidden (deferred) sync per step
    for (int t = 0; t < TT; t++) {
        float acc0[2][2][4];
        if (t + 1 < TT) {                     // gemm0(t+1): x-chunks BEFORE the wait
            ZACC(acc0);
            gemm_chunks<0>(smem, acc0, 0, nx, sp, t + 1);
        }
        dbar_wait(ws);                        // pw(t-1 epoch) globally complete
        if (t + 1 < TT) {                     // h0-dependent chunks + store
            gemm_chunks<0>(smem, acc0, nx, 4, sp, t + 1);
            store_part(acc0, g_part0, sp, col0);
        }
        {
            float acc1[2][2][4]; ZACC(acc1);
            gemm_chunks<1>(smem, acc1, 0, n1, sp, t);
            store_part(acc1, g_part1, sp, col0);
        }
        grid_sync(sense);                     // all partials visible
        if (hasCell) {
            pw_layer(g_part1, b1, Wc1, g_c1, g_h1h, g_h1l, out, t, true, cell);
            if (t + 1 < TT)
                pw_layer(g_part0, b0, Wc0, g_c0, g_h0h, g_h0l, out, t + 1, false, cell);
        }
        dbar_arrive(as);
    }
}

// ---------------- host launch ----------------
extern "C" void kernel_launch(void* const* d_in, const int* in_sizes, int n_in,
                              void* d_out, int out_size) {
    const float* x   = (const float*)d_in[0];
    const float* Wx0 = (const float*)d_in[1];
    const float* Wh0 = (const float*)d_in[2];
    const float* b0  = (const float*)d_in[3];
    const float* Wc0 = (const float*)d_in[4];
    const float* Wx1 = (const float*)d_in[5];
    const float* Wh1 = (const float*)d_in[6];
    const float* b1  = (const float*)d_in[7];
    const float* Wc1 = (const float*)d_in[8];
    float* out = (float*)d_out;

    cudaFuncSetAttribute(lstm_persistent,
                         cudaFuncAttributeMaxDynamicSharedMemorySize, SMEM_TOTAL);

    size_t total_conv = NW0E + NW1E + NXE;
    int conv_blocks = (int)((total_conv + 255) / 256);

    init_state<<<256, 256>>>();
    convert_all<<<conv_blocks, 256>>>(x, Wx0, Wh0, Wx1, Wh1);
    lstm_persistent<<<GRID, NTHREADS, SMEM_TOTAL>>>(b0, b1, Wc0, Wc1, out);
}

// round 13
// speedup vs baseline: 1.8174x; 1.2205x over previous
#include <cuda_runtime.h>
#include <cuda_fp16.h>
#include <math.h>
#include <stdint.h>

#define NB 64
#define TT 256
#define HH 1024
#define G3 3072
#define GRID 144
#define SPLITS 6
#define NTHREADS 512
#define K0 1536
#define K1 2048
#define CH1 32
#define W0_OFF 0
#define W1_OFF 65536
#define B_OFF 163840
#define B_STAGE 8192
#define SMEM_TOTAL 188416

typedef __half h16;

// ---------------- static device scratch ----------------
__device__ float g_c0[NB * HH];
__device__ float g_c1[NB * HH];
__device__ float g_part0[(size_t)SPLITS * NB * G3];
__device__ float g_part1[(size_t)SPLITS * NB * G3];
__device__ unsigned g_count, g_sense;     // full barrier
__device__ unsigned g_count2, g_sense2;   // deferred barrier

__device__ __align__(16) h16 g_h0[NB * HH];
__device__ __align__(16) h16 g_h1[NB * HH];
__device__ __align__(16) h16 g_x[(size_t)NB * TT * 512];
__device__ __align__(16) h16 g_W0[(size_t)G3 * K0];   // [Wx0|Wh0], rows [i|g|o]
__device__ __align__(16) h16 g_W1[(size_t)G3 * K1];   // [Wx1|Wh1]

// ---------------- helpers ----------------
__device__ __forceinline__ float sigmoid_(float x) {
    return __fdividef(1.0f, 1.0f + __expf(-x));
}
__device__ __forceinline__ float tanh_(float x) {
    return 1.0f - __fdividef(2.0f, __expf(2.0f * x) + 1.0f);
}

__device__ __forceinline__ uint32_t smem_u32(const void* p) {
    uint32_t a;
    asm("{ .reg .u64 t; cvta.to.shared.u64 t, %1; cvt.u32.u64 %0, t; }" : "=r"(a) : "l"(p));
    return a;
}
#define SWZ(x) ((x) ^ (((x) >> 3) & 0x70))

__device__ __forceinline__ void cp16(uint32_t dst, const void* src) {
    asm volatile("cp.async.cg.shared.global [%0], [%1], 16;" :: "r"(dst), "l"(src));
}
#define CP_COMMIT() asm volatile("cp.async.commit_group;" ::: "memory")

#define LDSM4(r, addr) \
    asm volatile("ldmatrix.sync.aligned.m8n8.x4.shared.b16 {%0,%1,%2,%3}, [%4];" \
        : "=r"((r)[0]), "=r"((r)[1]), "=r"((r)[2]), "=r"((r)[3]) : "r"(addr))

#define MMA(c, a, b0, b1) \
    asm volatile("mma.sync.aligned.m16n8k16.row.col.f32.f16.f16.f32 " \
        "{%0,%1,%2,%3},{%4,%5,%6,%7},{%8,%9},{%0,%1,%2,%3};" \
        : "+f"((c)[0]), "+f"((c)[1]), "+f"((c)[2]), "+f"((c)[3]) \
        : "r"((a)[0]), "r"((a)[1]), "r"((a)[2]), "r"((a)[3]), "r"(b0), "r"(b1))

// full sense-reversing grid barrier
__device__ __forceinline__ void grid_sync(int& sense) {
    sense ^= 1;
    __syncthreads();
    if (threadIdx.x == 0) {
        __threadfence();
        unsigned old = atomicAdd(&g_count, 1u);
        if (old == GRID - 1) {
            g_count = 0;
            asm volatile("st.global.release.gpu.u32 [%0], %1;"
                         :: "l"(&g_sense), "r"((unsigned)sense));
        } else {
            unsigned v;
            do {
                asm volatile("ld.global.acquire.gpu.u32 %0, [%1];"
                             : "=r"(v) : "l"(&g_sense));
            } while (v != (unsigned)sense);
        }
    }
    __syncthreads();
}

// deferred barrier: arrive (non-blocking) / wait (blocking), split in time
__device__ __forceinline__ void dbar_arrive(int& as) {
    as ^= 1;
    __syncthreads();                 // all CTA threads finished pw stores
    if (threadIdx.x == 0) {
        __threadfence();
        unsigned old = atomicAdd(&g_count2, 1u);
        if (old == GRID - 1) {
            g_count2 = 0;
            asm volatile("st.global.release.gpu.u32 [%0], %1;"
                         :: "l"(&g_sense2), "r"((unsigned)as));
        }
    }
}
__device__ __forceinline__ void dbar_wait(int& ws) {
    ws ^= 1;
    if (threadIdx.x == 0) {
        unsigned v;
        do {
            asm volatile("ld.global.acquire.gpu.u32 %0, [%1];"
                         : "=r"(v) : "l"(&g_sense2));
        } while (v != (unsigned)ws);
    }
    __syncthreads();
}

// ---------------- init / convert ----------------
__global__ void init_state() {
    int i = blockIdx.x * blockDim.x + threadIdx.x;
    if (i == 0) { g_count = 0u; g_sense = 0u; g_count2 = 0u; g_sense2 = 0u; }
    if (i < NB * HH) {
        g_c0[i] = 0.f; g_c1[i] = 0.f;
        h16 z = __float2half(0.f);
        g_h0[i] = z; g_h1[i] = z;
    }
}

#define NW0E ((size_t)G3 * K0)
#define NW1E ((size_t)G3 * K1)
#define NXE  ((size_t)NB * TT * 512)

__global__ void convert_all(const float* __restrict__ x,
    const float* __restrict__ Wx0, const float* __restrict__ Wh0,
    const float* __restrict__ Wx1, const float* __restrict__ Wh1)
{
    size_t idx = (size_t)blockIdx.x * 256 + threadIdx.x;
    if (idx < NW0E) {
        int r = (int)(idx / K0), k = (int)(idx % K0);
        int R = r + (r >= HH ? HH : 0);        // packed [i|g|o] -> orig [i,f,g,o]
        float v = (k < 512) ? Wx0[(size_t)R * 512 + k] : Wh0[(size_t)R * HH + (k - 512)];
        g_W0[idx] = __float2half(v);
    } else if (idx < NW0E + NW1E) {
        size_t i2 = idx - NW0E;
        int r = (int)(i2 / K1), k = (int)(i2 % K1);
        int R = r + (r >= HH ? HH : 0);
        float v = (k < HH) ? Wx1[(size_t)R * HH + k] : Wh1[(size_t)R * HH + (k - HH)];
        g_W1[i2] = __float2half(v);
    } else {
        size_t i2 = idx - NW0E - NW1E;
        if (i2 >= NXE) return;
        g_x[i2] = __float2half(x[i2]);
    }
}

// ---------------- smem tile loads (512 threads) ----------------
__device__ __forceinline__ void load_Wslot(uint32_t sbase,
    const h16* __restrict__ W, int k0, int ws, int tid)
{
#pragma unroll
    for (int i = 0; i < 2; i++) {
        int seg = tid + i * NTHREADS;          // 0..1023
        int row = seg >> 3, sc = seg & 7;
        uint32_t so = SWZ((uint32_t)(row * 128 + sc * 16));
        cp16(sbase + so, W + (size_t)row * ws + k0 + sc * 8);
    }
}
__device__ __forceinline__ void load_Bstage(uint32_t sbase,
    const h16* __restrict__ B, int k0, int bs, int tid)
{
    int row = tid >> 3, sc = tid & 7;          // 64 rows x 8 segs = 512
    uint32_t so = SWZ((uint32_t)(row * 128 + sc * 16));
    cp16(sbase + so, B + (size_t)row * bs + k0 + sc * 8);
}

// B source for a global chunk. L0: c<8 -> x(t) (STATIC), else h0. L1: c<16 -> h0, else h1.
template <int LAYER>
__device__ __forceinline__ void getB(int c, int t,
    const h16*& B, int& bk0, int& bs)
{
    if (LAYER == 0) {
        if (c < 8) { B = g_x + (size_t)t * 512; bs = TT * 512; bk0 = c * 64; }
        else       { B = g_h0; bs = HH; bk0 = (c - 8) * 64; }
    } else {
        if (c < 16) { B = g_h0; bs = HH; bk0 = c * 64; }
        else        { B = g_h1; bs = HH; bk0 = (c - 16) * 64; }
    }
}

// ---------------- warp MMA: 16 warps (4M x 4N), 1-term fp16 ----------------
__device__ __forceinline__ void compute_chunk(uint32_t wslot, uint32_t bstage,
    float acc[2][2][4], int lane, int warpM, int warpN)
{
#pragma unroll
    for (int kk = 0; kk < 4; kk++) {
        const int kByte = kk * 32;
        uint32_t ah[2][4];
#pragma unroll
        for (int mt = 0; mt < 2; mt++) {
            int row = warpM * 32 + mt * 16 + (lane & 7) + ((lane >> 3) & 1) * 8;
            int col = kByte + ((lane >> 4) << 4);
            LDSM4(ah[mt], wslot + SWZ((uint32_t)(row * 128 + col)));
        }
        uint32_t bh[4];
        {
            int row = warpN * 16 + (lane & 7) + ((lane >> 4) & 1) * 8;
            int col = kByte + (((lane >> 3) & 1) << 4);
            LDSM4(bh, bstage + SWZ((uint32_t)(row * 128 + col)));
        }
#pragma unroll
        for (int mt = 0; mt < 2; mt++)
#pragma unroll
            for (int nt = 0; nt < 2; nt++)
                MMA(acc[mt][nt], ah[mt], bh[nt * 2], bh[nt * 2 + 1]);
    }
}

// slot -> global chunk. gemm0 is round-robin (every split owns 1-2 static x-chunks).
template <int LAYER>
__device__ __forceinline__ int slot_chunk(int sp, int s) {
    return (LAYER == 0) ? (sp + SPLITS * s) : ((sp * CH1) / SPLITS + s);
}

// run pipeline over local W slots [s_begin, s_end), accumulating into acc
template <int LAYER>
__device__ __forceinline__ void gemm_chunks(uint32_t smem, float acc[2][2][4],
                                            int s_begin, int s_end, int sp, int t)
{
    if (s_begin >= s_end) return;
    const int tid = threadIdx.x;
    const int lane = tid & 31, wid = tid >> 5;
    const int warpM = wid & 3, warpN = wid >> 2;
    const uint32_t wbase = smem + (LAYER == 0 ? W0_OFF : W1_OFF);

    auto ldB = [&](int s) {
        const h16* B; int bk0, bs;
        getB<LAYER>(slot_chunk<LAYER>(sp, s), t, B, bk0, bs);
        load_Bstage(smem + B_OFF + (s % 3) * B_STAGE, B, bk0, bs, tid);
        CP_COMMIT();
    };
    ldB(s_begin);
    if (s_begin + 1 < s_end) ldB(s_begin + 1);
    for (int s = s_begin; s < s_end; s++) {
        if (s + 1 < s_end) { asm volatile("cp.async.wait_group 1;" ::: "memory"); }
        else               { asm volatile("cp.async.wait_group 0;" ::: "memory"); }
        __syncthreads();
        if (s + 2 < s_end) ldB(s + 2);
        compute_chunk(wbase + (uint32_t)s * 16384,
                      smem + B_OFF + (s % 3) * B_STAGE, acc, lane, warpM, warpN);
    }
    __syncthreads();
}

__device__ __forceinline__ void store_part(float acc[2][2][4], float* __restrict__ part,
                                           int sp, int col0)
{
    const int lane = threadIdx.x & 31, wid = threadIdx.x >> 5;
    const int warpM = wid & 3, warpN = wid >> 2;
    const int g = lane >> 2, tig = lane & 3;
#pragma unroll
    for (int mt = 0; mt < 2; mt++) {
        int colA = col0 + warpM * 32 + mt * 16 + g;
#pragma unroll
        for (int nt = 0; nt < 2; nt++) {
            int b = warpN * 16 + nt * 8 + tig * 2;
            float* p0 = part + ((size_t)sp * NB + b) * G3;
            p0[colA] = acc[mt][nt][0];
            p0[G3 + colA] = acc[mt][nt][1];
            p0[colA + 8] = acc[mt][nt][2];
            p0[G3 + colA + 8] = acc[mt][nt][3];
        }
    }
}

#define ZACC(a) do { \
_Pragma("unroll") for (int _i = 0; _i < 2; _i++) \
_Pragma("unroll") for (int _j = 0; _j < 2; _j++) \
_Pragma("unroll") for (int _k = 0; _k < 4; _k++) (a)[_i][_j][_k] = 0.f; } while (0)

// ---------------- pointwise (one layer, one cell per thread) ----------------
__device__ __forceinline__ void pw_layer(const float* __restrict__ part,
    const float* __restrict__ bias, const float* __restrict__ Wc,
    float* __restrict__ cb, h16* __restrict__ h_buf,
    float* __restrict__ out, int t, bool isL1, int cell)
{
    int b = cell >> 10, j = cell & (HH - 1);
    float si = 0.f, sg = 0.f, so = 0.f;
#pragma unroll
    for (int sp = 0; sp < SPLITS; sp++) {
        const float* p = part + ((size_t)sp * NB + b) * G3 + j;
        si += p[0]; sg += p[HH]; so += p[2 * HH];
    }
    float pi = si + bias[j];
    float pg = sg + bias[2 * HH + j];
    float po = so + bias[3 * HH + j];
    float c = cb[cell];
    float ig = sigmoid_(pi + Wc[j] * c);
    float gg = tanh_(pg);
    float og = sigmoid_(po + Wc[2 * HH + j] * c);
    float cn = gg * (c + ig);      // faithful: forget gate unused
    float hn = og * tanh_(c);      // faithful: uses OLD cell state
    cb[cell] = cn;
    h_buf[cell] = __float2half(hn);
    if (isL1) {
        out[((size_t)b * TT + t) * HH + j] = hn;
        if (t == TT - 1) {
            out[(size_t)NB * TT * HH + cell] = hn;
            out[(size_t)NB * TT * HH + NB * HH + cell] = cn;
        }
    }
}

__global__ __launch_bounds__(NTHREADS, 1) void lstm_persistent(
    const float* __restrict__ b0, const float* __restrict__ b1,
    const float* __restrict__ Wc0, const float* __restrict__ Wc1,
    float* __restrict__ out)
{
    extern __shared__ char smem_raw[];
    uint32_t smem = smem_u32(smem_raw);
    const int ct = blockIdx.x / SPLITS, sp = blockIdx.x % SPLITS;
    const int col0 = ct * 128;
    const int lo1 = (sp * CH1) / SPLITS, hi1 = ((sp + 1) * CH1) / SPLITS;
    const int n1 = hi1 - lo1;
    const int nx = (sp < 2) ? 2 : 1;           // static x slots in gemm0 round-robin
    const int tid = threadIdx.x;
    const int cell = blockIdx.x * NTHREADS + tid;
    const bool hasCell = (cell < NB * HH);

    // one-time: resident W slices (gemm0 slots round-robin: chunk sp + 6*s)
#pragma unroll
    for (int s = 0; s < 4; s++)
        load_Wslot(smem + W0_OFF + s * 16384, g_W0 + (size_t)col0 * K0,
                   (sp + SPLITS * s) * 64, K0, tid);
    for (int s = 0; s < n1; s++)
        load_Wslot(smem + W1_OFF + s * 16384, g_W1 + (size_t)col0 * K1,
                   (lo1 + s) * 64, K1, tid);
    CP_COMMIT();
    asm volatile("cp.async.wait_group 0;" ::: "memory");
    __syncthreads();

    int sense = 0, as = 0, ws = 0;
    // ---- prologue: h0(0) (h0/h1 initial zeros already global-visible)
    {
        float acc[2][2][4]; ZACC(acc);
        gemm_chunks<0>(smem, acc, 0, 4, sp, 0);
        store_part(acc, g_part0, sp, col0);
        grid_sync(sense);
        if (hasCell) pw_layer(g_part0, b0, Wc0, g_c0, g_h0, out, 0, false, cell);
        dbar_arrive(as);
    }

    // ---- steady state: 1 blocking sync + 1 hidden (deferred) sync per step
    for (int t = 0; t < TT; t++) {
        float acc0[2][2][4];
        if (t + 1 < TT) {                     // gemm0(t+1): x-chunks BEFORE the wait
            ZACC(acc0);
            gemm_chunks<0>(smem, acc0, 0, nx, sp, t + 1);
        }
        dbar_wait(ws);                        // pw(t-1 epoch) globally complete
        if (t + 1 < TT) {                     // h0-dependent chunks + store
            gemm_chunks<0>(smem, acc0, nx, 4, sp, t + 1);
            store_part(acc0, g_part0, sp, col0);
        }
        {
            float acc1[2][2][4]; ZACC(acc1);
            gemm_chunks<1>(smem, acc1, 0, n1, sp, t);
            store_part(acc1, g_part1, sp, col0);
        }
        grid_sync(sense);                     // all partials visible
        if (hasCell) {
            pw_layer(g_part1, b1, Wc1, g_c1, g_h1, out, t, true, cell);
            if (t + 1 < TT)
                pw_layer(g_part0, b0, Wc0, g_c0, g_h0, out, t + 1, false, cell);
        }
        dbar_arrive(as);
    }
}

// ---------------- host launch ----------------
extern "C" void kernel_launch(void* const* d_in, const int* in_sizes, int n_in,
                              void* d_out, int out_size) {
    const float* x   = (const float*)d_in[0];
    const float* Wx0 = (const float*)d_in[1];
    const float* Wh0 = (const float*)d_in[2];
    const float* b0  = (const float*)d_in[3];
    const float* Wc0 = (const float*)d_in[4];
    const float* Wx1 = (const float*)d_in[5];
    const float* Wh1 = (const float*)d_in[6];
    const float* b1  = (const float*)d_in[7];
    const float* Wc1 = (const float*)d_in[8];
    float* out = (float*)d_out;

    cudaFuncSetAttribute(lstm_persistent,
                         cudaFuncAttributeMaxDynamicSharedMemorySize, SMEM_TOTAL);

    size_t total_conv = NW0E + NW1E + NXE;
    int conv_blocks = (int)((total_conv + 255) / 256);

    init_state<<<256, 256>>>();
    convert_all<<<conv_blocks, 256>>>(x, Wx0, Wh0, Wx1, Wh1);
    lstm_persistent<<<GRID, NTHREADS, SMEM_TOTAL>>>(b0, b1, Wc0, Wc1, out);
}